// round 2
// baseline (speedup 1.0000x reference)
#include <cuda_runtime.h>
#include <math.h>

#define WPC 8   // warps (pixels) per CTA

namespace {
constexpr int kB  = 2;
constexpr int kC  = 128;
constexpr int kHd = 64;
constexpr int kWd = 96;
constexpr int kHu = 128;
constexpr int kWu = 192;
constexpr int kN  = kB * kHu * kWu;   // 49152 pixels
}

// Precombined final-head weights:
//   fin = [xf, cf, xf-cf]  =>  fin@W = xf@(W0+W2) + cf@(W1-W2)
__device__ float g_WA[128 * 384];
__device__ float g_WB[128 * 384];

__global__ void prep_kernel(const float* __restrict__ o1w) {
    int i = blockIdx.x * blockDim.x + threadIdx.x;
    if (i < 128 * 384) {
        int in = i / 384, o = i - in * 384;
        float w2 = o1w[(256 + in) * 384 + o];
        g_WA[i] = o1w[in * 384 + o] + w2;
        g_WB[i] = o1w[(128 + in) * 384 + o] - w2;
    }
}

__device__ __forceinline__ float wsum(float v) {
#pragma unroll
    for (int o = 16; o; o >>= 1) v += __shfl_xor_sync(0xffffffffu, v, o);
    return v;
}

__device__ __forceinline__ float4 ldg4(const float* p) {
    return __ldg(reinterpret_cast<const float4*>(p));
}

// y[r*128 + lane*4 .. +3] += sum_in xs[in] * W[in*STRIDE + r*128 + lane*4 ..]
template <int NG, int STRIDE>
__device__ __forceinline__ void mv(const float* __restrict__ W, const float* xs,
                                   int o4, float4* a) {
#pragma unroll 4
    for (int in = 0; in < 128; ++in) {
        float xv = xs[in];
#pragma unroll
        for (int r = 0; r < NG; ++r) {
            float4 wv = ldg4(W + in * STRIDE + r * 128 + o4);
            a[r].x = fmaf(xv, wv.x, a[r].x);
            a[r].y = fmaf(xv, wv.y, a[r].y);
            a[r].z = fmaf(xv, wv.z, a[r].z);
            a[r].w = fmaf(xv, wv.w, a[r].w);
        }
    }
}

// LayerNorm over 128 channels distributed 4/lane across the warp
__device__ __forceinline__ void ln4(const float v[4], float eps, float o[4]) {
    float m = wsum(v[0] + v[1] + v[2] + v[3]) * (1.0f / 128.0f);
    float q = wsum(v[0] * v[0] + v[1] * v[1] + v[2] * v[2] + v[3] * v[3]) * (1.0f / 128.0f);
    float r = rsqrtf(fmaxf(q - m * m, 0.0f) + eps);
#pragma unroll
    for (int i = 0; i < 4; ++i) o[i] = (v[i] - m) * r;
}

__device__ __forceinline__ float gelu_tanh(float x) {
    float u = 0.7978845608028654f * (x + 0.044715f * x * x * x);
    return 0.5f * x * (1.0f + tanhf(u));
}
__device__ __forceinline__ float gelu_erf(float x) {
    return 0.5f * x * (1.0f + erff(x * 0.7071067811865475f));
}

__global__ __launch_bounds__(WPC * 32)
void upsample_tf_kernel(
    const float* __restrict__ feat, const float* __restrict__ featup,
    const float* __restrict__ ctx_ln_b,
    const float* __restrict__ q_w, const float* __restrict__ q_b,
    const float* __restrict__ k_w, const float* __restrict__ k_b,
    const float* __restrict__ v_w, const float* __restrict__ v_b,
    const float* __restrict__ o_w, const float* __restrict__ o_b,
    const float* __restrict__ fc1_w, const float* __restrict__ fc1_b,
    const float* __restrict__ fc2_w, const float* __restrict__ fc2_b,
    const float* __restrict__ out1_b,
    const float* __restrict__ out2_w, const float* __restrict__ out2_b,
    const float* __restrict__ ctx_ln_g,
    float* __restrict__ out)
{
    __shared__ float s_x[WPC][128];      // xn / q / o / h / xf
    __shared__ float s_c[WPC][4][128];   // cn -> v ; later cf
    __shared__ float s_k[WPC][512];      // k (4x128) ; later fc1 hidden (512)
    __shared__ float s_a[WPC][16];       // attention weights

    const int w  = threadIdx.x >> 5;
    const int ln = threadIdx.x & 31;
    const int o4 = ln * 4;
    const int n  = blockIdx.x * WPC + w;
    if (n >= kN) return;   // uniform per warp

    const int b  = n / (kHu * kWu);
    const int rr = n - b * (kHu * kWu);
    const int hu = rr / kWu;
    const int wu = rr - hu * kWu;

    float* xb = s_x[w];
    float (*cb)[128] = s_c[w];
    float* kb = s_k[w];
    float* ab = s_a[w];

    // clipped 2x2 window (replicate pad)
    const int rh0 = min(hu >> 1, kHd - 1), rh1 = min((hu >> 1) + 1, kHd - 1);
    const int rw0 = min(wu >> 1, kWd - 1), rw1 = min((wu >> 1) + 1, kWd - 1);
    const int rh[2] = {rh0, rh1};
    const int rw[2] = {rw0, rw1};

    // ---- load x (feat_map_up pixel) and ctx (4 window pixels), channels in regs
    float x[4], ctx[4][4];
    {
        const float* fu = featup + ((size_t)b * kC) * (kHu * kWu) + (size_t)hu * kWu + wu;
#pragma unroll
        for (int i = 0; i < 4; ++i)
            x[i] = __ldg(fu + (size_t)(o4 + i) * (kHu * kWu));
        const float* fm = feat + ((size_t)b * kC) * (kHd * kWd);
#pragma unroll
        for (int j = 0; j < 4; ++j) {
            int base = rh[j >> 1] * kWd + rw[j & 1];
#pragma unroll
            for (int i = 0; i < 4; ++i)
                ctx[j][i] = __ldg(fm + (size_t)(o4 + i) * (kHd * kWd) + base);
        }
    }

    // ---- transformer blocks
#pragma unroll 1
    for (int l = 0; l < 2; ++l) {
        const float* qW  = q_w  + l * 128 * 128;
        const float* kW  = k_w  + l * 128 * 128;
        const float* vW  = v_w  + l * 128 * 128;
        const float* oW  = o_w  + l * 128 * 128;
        const float* f1W = fc1_w + l * 128 * 512;
        const float* f2W = fc2_w + l * 512 * 128;

        // xn = LN(x)
        float xn[4];
        ln4(x, 1e-6f, xn);
        __syncwarp();
#pragma unroll
        for (int i = 0; i < 4; ++i) xb[o4 + i] = xn[i];

        // cn = LN(ctx, 1e-5)*g + b
        {
            float4 g = ldg4(ctx_ln_g + l * 128 + o4);
            float4 be = ldg4(ctx_ln_b + l * 128 + o4);
#pragma unroll
            for (int j = 0; j < 4; ++j) {
                float cn[4];
                ln4(ctx[j], 1e-5f, cn);
                cb[j][o4 + 0] = cn[0] * g.x + be.x;
                cb[j][o4 + 1] = cn[1] * g.y + be.y;
                cb[j][o4 + 2] = cn[2] * g.z + be.z;
                cb[j][o4 + 3] = cn[3] * g.w + be.w;
            }
        }
        __syncwarp();

        // q = xn @ q_w + q_b
        float4 qa = ldg4(q_b + l * 128 + o4);
        mv<1, 128>(qW, xb, o4, &qa);

        // k rows
#pragma unroll 1
        for (int j = 0; j < 4; ++j) {
            float4 ka = ldg4(k_b + l * 128 + o4);
            mv<1, 128>(kW, cb[j], o4, &ka);
            *reinterpret_cast<float4*>(kb + j * 128 + o4) = ka;
        }
        __syncwarp();                 // all xb (xn) reads done
        *reinterpret_cast<float4*>(xb + o4) = qa;   // xb now holds q

        // v rows, overwriting cn row-by-row
#pragma unroll 1
        for (int j = 0; j < 4; ++j) {
            float4 va = ldg4(v_b + l * 128 + o4);
            mv<1, 128>(vW, cb[j], o4, &va);
            __syncwarp();             // all reads of cb[j] done
            *reinterpret_cast<float4*>(&cb[j][o4]) = va;
        }
        __syncwarp();                 // q, k, v visible

        // ---- attention: lanes 0..15 each handle one (head h, key j)
        if (ln < 16) {
            int h = ln >> 2, j = ln & 3;
            const float* qp = xb + h * 32;
            const float* kp = kb + j * 128 + h * 32;
            float s = 0.0f;
#pragma unroll
            for (int d = 0; d < 32; ++d) s = fmaf(qp[d], kp[d], s);
            int ky = j >> 1, kx = j & 1;
            float cd = -(float)abs(hu - 2 * rh[ky]) - (float)abs(wu - 2 * rw[kx]);
            float slope = exp2f(-(float)(h + 1) * 1.1462406251802891f); // log2(24)/4
            s = s * 0.17677669529663687f + slope * cd;
            float m = s;
            m = fmaxf(m, __shfl_xor_sync(0x0000ffffu, m, 1));
            m = fmaxf(m, __shfl_xor_sync(0x0000ffffu, m, 2));
            float e = expf(s - m);
            float se = e;
            se += __shfl_xor_sync(0x0000ffffu, se, 1);
            se += __shfl_xor_sync(0x0000ffffu, se, 2);
            ab[ln] = e / se;
        }
        __syncwarp();

        // o = attn @ v  (v lives in cb)
        float o_[4];
        {
            int h = ln >> 3;
            float a0 = ab[h * 4 + 0], a1 = ab[h * 4 + 1], a2 = ab[h * 4 + 2], a3 = ab[h * 4 + 3];
#pragma unroll
            for (int i = 0; i < 4; ++i) {
                float acc = a0 * cb[0][o4 + i];
                acc = fmaf(a1, cb[1][o4 + i], acc);
                acc = fmaf(a2, cb[2][o4 + i], acc);
                acc = fmaf(a3, cb[3][o4 + i], acc);
                o_[i] = acc;
            }
        }
        __syncwarp();
#pragma unroll
        for (int i = 0; i < 4; ++i) xb[o4 + i] = o_[i];
        __syncwarp();

        // x += o @ o_w + o_b
        {
            float4 oa = ldg4(o_b + l * 128 + o4);
            mv<1, 128>(oW, xb, o4, &oa);
            x[0] += oa.x; x[1] += oa.y; x[2] += oa.z; x[3] += oa.w;
        }

        // MLP: x += gelu_tanh(LN(x) @ fc1 + b1) @ fc2 + b2
        float hn[4];
        ln4(x, 1e-6f, hn);
        __syncwarp();                 // o-proj reads of xb done
#pragma unroll
        for (int i = 0; i < 4; ++i) xb[o4 + i] = hn[i];
        __syncwarp();

        float4 f1a[4];
#pragma unroll
        for (int r = 0; r < 4; ++r) f1a[r] = ldg4(fc1_b + l * 512 + r * 128 + o4);
        mv<4, 512>(f1W, xb, o4, f1a);
        __syncwarp();                 // kb (k) reads done at attention
#pragma unroll
        for (int r = 0; r < 4; ++r) {
            kb[r * 128 + o4 + 0] = gelu_tanh(f1a[r].x);
            kb[r * 128 + o4 + 1] = gelu_tanh(f1a[r].y);
            kb[r * 128 + o4 + 2] = gelu_tanh(f1a[r].z);
            kb[r * 128 + o4 + 3] = gelu_tanh(f1a[r].w);
        }
        __syncwarp();

        {
            float4 f2a = ldg4(fc2_b + l * 128 + o4);
#pragma unroll 4
            for (int in = 0; in < 512; ++in) {
                float hv = kb[in];
                float4 wv = ldg4(f2W + in * 128 + o4);
                f2a.x = fmaf(hv, wv.x, f2a.x);
                f2a.y = fmaf(hv, wv.y, f2a.y);
                f2a.z = fmaf(hv, wv.z, f2a.z);
                f2a.w = fmaf(hv, wv.w, f2a.w);
            }
            x[0] += f2a.x; x[1] += f2a.y; x[2] += f2a.z; x[3] += f2a.w;
        }
        __syncwarp();                 // kb reads done before next layer writes
    }

    // ---- final head
    float xf[4];
    ln4(x, 1e-6f, xf);
#pragma unroll
    for (int i = 0; i < 4; ++i) xb[o4 + i] = xf[i];
#pragma unroll
    for (int j = 0; j < 4; ++j) {
        float cf[4];
        ln4(ctx[j], 1e-6f, cf);
#pragma unroll
        for (int i = 0; i < 4; ++i) cb[j][o4 + i] = cf[i];
    }
    __syncwarp();

    // t_base = out1_b + xf @ WA   (shared across all 4 rows)
    float4 tb[3];
#pragma unroll
    for (int r = 0; r < 3; ++r) tb[r] = ldg4(out1_b + r * 128 + o4);
    mv<3, 384>(g_WA, xb, o4, tb);

    float4 w2[3];
#pragma unroll
    for (int r = 0; r < 3; ++r) w2[r] = ldg4(out2_w + r * 128 + o4);
    const float o2b = __ldg(out2_b);

    float logit[4];
#pragma unroll 1
    for (int j = 0; j < 4; ++j) {
        float4 u[3];
        u[0] = make_float4(0.f, 0.f, 0.f, 0.f);
        u[1] = make_float4(0.f, 0.f, 0.f, 0.f);
        u[2] = make_float4(0.f, 0.f, 0.f, 0.f);
        mv<3, 384>(g_WB, cb[j], o4, u);
        float p = 0.0f;
#pragma unroll
        for (int r = 0; r < 3; ++r) {
            p += gelu_erf(tb[r].x + u[r].x) * w2[r].x;
            p += gelu_erf(tb[r].y + u[r].y) * w2[r].y;
            p += gelu_erf(tb[r].z + u[r].z) * w2[r].z;
            p += gelu_erf(tb[r].w + u[r].w) * w2[r].w;
        }
        logit[j] = wsum(p) + o2b;
    }

    // softmax over the 4 window logits, write (B, K2, Hu, Wu)
    float mx = fmaxf(fmaxf(logit[0], logit[1]), fmaxf(logit[2], logit[3]));
    float e0 = expf(logit[0] - mx), e1 = expf(logit[1] - mx);
    float e2 = expf(logit[2] - mx), e3 = expf(logit[3] - mx);
    float inv = 1.0f / (e0 + e1 + e2 + e3);
    if (ln < 4) {
        float ev = (ln == 0) ? e0 : (ln == 1) ? e1 : (ln == 2) ? e2 : e3;
        out[(((size_t)b * 4 + ln) * kHu + hu) * kWu + wu] = ev * inv;
    }
}

extern "C" void kernel_launch(void* const* d_in, const int* in_sizes, int n_in,
                              void* d_out, int out_size) {
    const float* feat     = (const float*)d_in[0];
    const float* featup   = (const float*)d_in[1];
    const float* ctx_ln_b = (const float*)d_in[2];
    const float* q_w      = (const float*)d_in[3];
    const float* q_b      = (const float*)d_in[4];
    const float* k_w      = (const float*)d_in[5];
    const float* k_b      = (const float*)d_in[6];
    const float* v_w      = (const float*)d_in[7];
    const float* v_b      = (const float*)d_in[8];
    const float* o_w      = (const float*)d_in[9];
    const float* o_b      = (const float*)d_in[10];
    const float* fc1_w    = (const float*)d_in[11];
    const float* fc1_b    = (const float*)d_in[12];
    const float* fc2_w    = (const float*)d_in[13];
    const float* fc2_b    = (const float*)d_in[14];
    const float* out1_w   = (const float*)d_in[15];
    const float* out1_b   = (const float*)d_in[16];
    const float* out2_w   = (const float*)d_in[17];
    const float* out2_b   = (const float*)d_in[18];
    const float* ctx_ln_g = (const float*)d_in[19];

    prep_kernel<<<(128 * 384 + 255) / 256, 256>>>(out1_w);
    upsample_tf_kernel<<<kN / WPC, WPC * 32>>>(
        feat, featup, ctx_ln_b, q_w, q_b, k_w, k_b, v_w, v_b, o_w, o_b,
        fc1_w, fc1_b, fc2_w, fc2_b, out1_b, out2_w, out2_b, ctx_ln_g,
        (float*)d_out);
}

// round 4
// speedup vs baseline: 1.2931x; 1.2931x over previous
#include <cuda_runtime.h>
#include <math.h>

typedef unsigned long long ull;

namespace {
constexpr int kB = 2, kC = 128, kHd = 64, kWd = 96, kHu = 128, kWu = 192;
constexpr int kN = kB * kHu * kWu;
constexpr int kHWd = kHd * kWd, kHWu = kHu * kWu;
}

// Precombined final-head weights: fin=[xf,cf,xf-cf] => fin@W = xf@(W0+W2) + cf@(W1-W2)
__device__ float g_WA[128 * 384];
__device__ float g_WB[128 * 384];

__global__ void prep_kernel(const float* __restrict__ o1w) {
    int i = blockIdx.x * blockDim.x + threadIdx.x;
    if (i < 128 * 384) {
        int in = i / 384, o = i - in * 384;
        float w2 = o1w[(256 + in) * 384 + o];
        g_WA[i] = o1w[in * 384 + o] + w2;
        g_WB[i] = o1w[(128 + in) * 384 + o] - w2;
    }
}

// ---- packed f32x2 helpers (SASS FFMA2 path, PTX-only) ----
__device__ __forceinline__ ull pk2(float a, float b) {
    ull r; asm("mov.b64 %0,{%1,%2};" : "=l"(r) : "f"(a), "f"(b)); return r;
}
__device__ __forceinline__ ull dup2(float a) { return pk2(a, a); }
__device__ __forceinline__ void up2(ull v, float& a, float& b) {
    asm("mov.b64 {%0,%1},%2;" : "=f"(a), "=f"(b) : "l"(v));
}
__device__ __forceinline__ ull fma2(ull a, ull b, ull c) {
    ull d; asm("fma.rn.f32x2 %0,%1,%2,%3;" : "=l"(d) : "l"(a), "l"(b), "l"(c)); return d;
}
__device__ __forceinline__ ull add2(ull a, ull b) {
    ull d; asm("add.rn.f32x2 %0,%1,%2;" : "=l"(d) : "l"(a), "l"(b)); return d;
}
__device__ __forceinline__ ull mul2(ull a, ull b) {
    ull d; asm("mul.rn.f32x2 %0,%1,%2;" : "=l"(d) : "l"(a), "l"(b)); return d;
}

// pixel-pair-interleaved smem with XOR bank swizzle.
// Each "slot" f2 holds one 64-bit pixel-pair at float offset 2*swz(f2).
// A 128-channel activation (2 pixel-pairs) occupies 512 floats.
__device__ __forceinline__ int swzi(int f2) { return f2 ^ ((f2 >> 4) & 15); }
__device__ __forceinline__ ull ldp(const float* b, int f2) {
    return *reinterpret_cast<const ull*>(b + 2 * swzi(f2));
}
__device__ __forceinline__ void stp(float* b, int f2, ull v) {
    *reinterpret_cast<ull*>(b + 2 * swzi(f2)) = v;
}

__device__ __forceinline__ ull wsum2(ull v) {
#pragma unroll
    for (int o = 16; o; o >>= 1) v = add2(v, __shfl_xor_sync(0xffffffffu, v, o));
    return v;
}

// LayerNorm of one pixel-pair: v[i] packs channel (o4+i) of two pixels
__device__ __forceinline__ void ln2(const ull v[4], float eps, ull o[4]) {
    ull s = add2(add2(v[0], v[1]), add2(v[2], v[3]));
    ull q = fma2(v[0], v[0], fma2(v[1], v[1], fma2(v[2], v[2], mul2(v[3], v[3]))));
    s = wsum2(s); q = wsum2(q);
    float s0, s1, q0, q1; up2(s, s0, s1); up2(q, q0, q1);
    float m0 = s0 * (1.0f / 128.0f), m1 = s1 * (1.0f / 128.0f);
    float r0 = rsqrtf(fmaxf(q0 * (1.0f / 128.0f) - m0 * m0, 0.0f) + eps);
    float r1 = rsqrtf(fmaxf(q1 * (1.0f / 128.0f) - m1 * m1, 0.0f) + eps);
    ull nm = pk2(-m0, -m1), rr = pk2(r0, r1);
#pragma unroll
    for (int i = 0; i < 4; ++i) o[i] = mul2(add2(v[i], nm), rr);
}

__device__ __forceinline__ float gelu_t(float x) {
    float u = 0.7978845608028654f * (x + 0.044715f * x * x * x);
    return 0.5f * x * (1.0f + tanhf(u));
}
__device__ __forceinline__ ull gelu_t2(ull v) { float a, b; up2(v, a, b); return pk2(gelu_t(a), gelu_t(b)); }
__device__ __forceinline__ float gelu_e(float x) { return 0.5f * x * (1.0f + erff(x * 0.7071067811865475f)); }
__device__ __forceinline__ ull gelu_e2(ull v) { float a, b; up2(v, a, b); return pk2(gelu_e(a), gelu_e(b)); }

__device__ __forceinline__ float4 ldg4(const float* p) {
    return __ldg(reinterpret_cast<const float4*>(p));
}

// Packed multi-row GEMV:
// acc[row][pair][r*4+i] += sum_in act[row](in,pair) * W[in*STRIDE + r*128 + o4 + i]
template <int NIN, int ROWS, int NG, int STRIDE>
__device__ __forceinline__ void mv2(const float* __restrict__ W, const float* __restrict__ act,
                                    int actStride, int o4, ull* acc) {
#pragma unroll 2
    for (int in = 0; in < NIN; ++in) {
        ull wd[NG][4];
#pragma unroll
        for (int r = 0; r < NG; ++r) {
            float4 wv = ldg4(W + in * STRIDE + r * 128 + o4);
            wd[r][0] = dup2(wv.x); wd[r][1] = dup2(wv.y);
            wd[r][2] = dup2(wv.z); wd[r][3] = dup2(wv.w);
        }
#pragma unroll
        for (int row = 0; row < ROWS; ++row) {
            ull a0 = ldp(act + row * actStride, in * 2 + 0);
            ull a1 = ldp(act + row * actStride, in * 2 + 1);
            ull* ar = acc + row * (2 * NG * 4);
#pragma unroll
            for (int r = 0; r < NG; ++r)
#pragma unroll
                for (int i = 0; i < 4; ++i) {
                    ar[r * 4 + i]          = fma2(a0, wd[r][i], ar[r * 4 + i]);
                    ar[NG * 4 + r * 4 + i] = fma2(a1, wd[r][i], ar[NG * 4 + r * 4 + i]);
                }
        }
    }
}

__global__ __launch_bounds__(64)
void upsample_tf_kernel(
    const float* __restrict__ feat, const float* __restrict__ featup,
    const float* __restrict__ ctx_ln_b,
    const float* __restrict__ q_w, const float* __restrict__ q_b,
    const float* __restrict__ k_w, const float* __restrict__ k_b,
    const float* __restrict__ v_w, const float* __restrict__ v_b,
    const float* __restrict__ o_w, const float* __restrict__ o_b,
    const float* __restrict__ fc1_w, const float* __restrict__ fc1_b,
    const float* __restrict__ fc2_w, const float* __restrict__ fc2_b,
    const float* __restrict__ out1_b,
    const float* __restrict__ out2_w, const float* __restrict__ out2_b,
    const float* __restrict__ ctx_ln_g,
    float* __restrict__ out)
{
    // paired layout: 128-ch vector = 512 floats; fc1 hidden (512-ch) = 2048 floats
    __shared__ __align__(16) float s_x[2][512];       // xn/q/o/hn/xf
    __shared__ __align__(16) float s_c[2][4][512];    // cn / cf
    __shared__ __align__(16) float s_k[2][2048];      // k rows / fc1 hidden
    __shared__ __align__(16) float s_a[2][4][16];     // attn weights / logits

    const int w = threadIdx.x >> 5, ln = threadIdx.x & 31, o4 = ln * 4;
    const int g = blockIdx.x * 2 + w;   // group of 4 consecutive pixels (same row)
    const int n0 = g * 4;
    if (n0 >= kN) return;
    const int b = n0 / kHWu;
    const int rr = n0 - b * kHWu;
    const int hu = rr / kWu, wu0 = rr - hu * kWu;

    float* sx = s_x[w];
    float* sc = &s_c[w][0][0];
    float* sk = s_k[w];
    float (*sa)[16] = s_a[w];

    const int rh0 = min(hu >> 1, kHd - 1), rh1 = min((hu >> 1) + 1, kHd - 1);

    // ---- x load (4 consecutive pixels -> vectorized), packed into pixel pairs
    ull x2[2][4];
    {
        const float* fu = featup + ((size_t)b * kC) * kHWu + (size_t)hu * kWu + wu0;
#pragma unroll
        for (int i = 0; i < 4; ++i) {
            float4 p = ldg4(fu + (size_t)(o4 + i) * kHWu);
            x2[0][i] = pk2(p.x, p.y);
            x2[1][i] = pk2(p.z, p.w);
        }
    }

    // ctx window loader (raw values, reloaded per use to save registers; L1-hot)
    auto loadctx = [&](int j, ull cv[2][4]) {
        const int ky = j >> 1, kx = j & 1;
        const int rhv = ky ? rh1 : rh0;
        const float* fm = feat + ((size_t)b * kC) * kHWd + rhv * kWd;
#pragma unroll
        for (int i = 0; i < 4; ++i) {
            const float* cp = fm + (size_t)(o4 + i) * kHWd;
            float v0 = __ldg(cp + min(((wu0 + 0) >> 1) + kx, kWd - 1));
            float v1 = __ldg(cp + min(((wu0 + 1) >> 1) + kx, kWd - 1));
            float v2 = __ldg(cp + min(((wu0 + 2) >> 1) + kx, kWd - 1));
            float v3 = __ldg(cp + min(((wu0 + 3) >> 1) + kx, kWd - 1));
            cv[0][i] = pk2(v0, v1);
            cv[1][i] = pk2(v2, v3);
        }
    };

    // ---- transformer blocks
#pragma unroll 1
    for (int l = 0; l < 2; ++l) {
        const float* qW  = q_w  + l * 16384;
        const float* kW  = k_w  + l * 16384;
        const float* vW  = v_w  + l * 16384;
        const float* oW  = o_w  + l * 16384;
        const float* f1W = fc1_w + l * 65536;
        const float* f2W = fc2_w + l * 65536;

        // xn = LN(x)
        ull t2[2][4];
        ln2(x2[0], 1e-6f, t2[0]);
        ln2(x2[1], 1e-6f, t2[1]);
        __syncwarp();   // prior readers of sx/sk done
#pragma unroll
        for (int pr = 0; pr < 2; ++pr)
#pragma unroll
            for (int i = 0; i < 4; ++i) stp(sx, (o4 + i) * 2 + pr, t2[pr][i]);

        // cn = LN(ctx,1e-5)*g + b
        {
            float4 gg = ldg4(ctx_ln_g + l * 128 + o4);
            float4 bb = ldg4(ctx_ln_b + l * 128 + o4);
            ull gd[4] = {dup2(gg.x), dup2(gg.y), dup2(gg.z), dup2(gg.w)};
            ull bd[4] = {dup2(bb.x), dup2(bb.y), dup2(bb.z), dup2(bb.w)};
#pragma unroll 1
            for (int j = 0; j < 4; ++j) {
                ull cv[2][4], cn[2][4];
                loadctx(j, cv);
                ln2(cv[0], 1e-5f, cn[0]);
                ln2(cv[1], 1e-5f, cn[1]);
#pragma unroll
                for (int pr = 0; pr < 2; ++pr)
#pragma unroll
                    for (int i = 0; i < 4; ++i)
                        stp(sc + j * 512, (o4 + i) * 2 + pr, fma2(cn[pr][i], gd[i], bd[i]));
            }
        }
        __syncwarp();

        // q = xn @ q_w + q_b
        ull qa[2][4];
        {
            float4 qb = ldg4(q_b + l * 128 + o4);
            qa[0][0] = qa[1][0] = dup2(qb.x); qa[0][1] = qa[1][1] = dup2(qb.y);
            qa[0][2] = qa[1][2] = dup2(qb.z); qa[0][3] = qa[1][3] = dup2(qb.w);
        }
        mv2<128, 1, 1, 128>(qW, sx, 0, o4, &qa[0][0]);

        // k (4 ctx rows at once)
        ull ka[4][2][4];
        {
            float4 kb = ldg4(k_b + l * 128 + o4);
#pragma unroll
            for (int j = 0; j < 4; ++j) {
                ka[j][0][0] = ka[j][1][0] = dup2(kb.x); ka[j][0][1] = ka[j][1][1] = dup2(kb.y);
                ka[j][0][2] = ka[j][1][2] = dup2(kb.z); ka[j][0][3] = ka[j][1][3] = dup2(kb.w);
            }
        }
        mv2<128, 4, 1, 128>(kW, sc, 512, o4, &ka[0][0][0]);

        // v (stays in registers through attention)
        ull va[4][2][4];
        {
            float4 vb = ldg4(v_b + l * 128 + o4);
#pragma unroll
            for (int j = 0; j < 4; ++j) {
                va[j][0][0] = va[j][1][0] = dup2(vb.x); va[j][0][1] = va[j][1][1] = dup2(vb.y);
                va[j][0][2] = va[j][1][2] = dup2(vb.z); va[j][0][3] = va[j][1][3] = dup2(vb.w);
            }
        }
        mv2<128, 4, 1, 128>(vW, sc, 512, o4, &va[0][0][0]);
        __syncwarp();   // xn/cn reads complete

#pragma unroll
        for (int j = 0; j < 4; ++j)
#pragma unroll
            for (int pr = 0; pr < 2; ++pr)
#pragma unroll
                for (int i = 0; i < 4; ++i) stp(sk + j * 512, (o4 + i) * 2 + pr, ka[j][pr][i]);
#pragma unroll
        for (int pr = 0; pr < 2; ++pr)
#pragma unroll
            for (int i = 0; i < 4; ++i) stp(sx, (o4 + i) * 2 + pr, qa[pr][i]);
        __syncwarp();

        // ---- attention scores: lanes 0..15 = (head h, key j); packed dot = 2 pixels at once
        if (ln < 16) {
            const int h = ln >> 2, j = ln & 3, ky = j >> 1, kx = j & 1;
            const int rhv = ky ? rh1 : rh0;
            const float slope = exp2f(-(float)(h + 1) * 1.1462406251802891f); // log2(24)/4
#pragma unroll
            for (int pr = 0; pr < 2; ++pr) {
                ull accA = pk2(0.f, 0.f), accB = pk2(0.f, 0.f);
#pragma unroll
                for (int d = 0; d < 32; d += 2) {
                    accA = fma2(ldp(sx, (h * 32 + d) * 2 + pr),
                                ldp(sk + j * 512, (h * 32 + d) * 2 + pr), accA);
                    accB = fma2(ldp(sx, (h * 32 + d + 1) * 2 + pr),
                                ldp(sk + j * 512, (h * 32 + d + 1) * 2 + pr), accB);
                }
                float sA, sB; up2(add2(accA, accB), sA, sB);
#pragma unroll
                for (int t = 0; t < 2; ++t) {
                    int p = pr * 2 + t;
                    float sv = t ? sB : sA;
                    int wup = wu0 + p;
                    int rwv = min((wup >> 1) + kx, kWd - 1);
                    float cd = -(float)(abs(hu - 2 * rhv) + abs(wup - 2 * rwv));
                    float s = sv * 0.17677669529663687f + slope * cd;
                    float m = s;
                    m = fmaxf(m, __shfl_xor_sync(0x0000ffffu, m, 1));
                    m = fmaxf(m, __shfl_xor_sync(0x0000ffffu, m, 2));
                    float e = expf(s - m);
                    float se = e;
                    se += __shfl_xor_sync(0x0000ffffu, se, 1);
                    se += __shfl_xor_sync(0x0000ffffu, se, 2);
                    sa[p][ln] = e / se;   // ln == h*4 + j
                }
            }
        }
        __syncwarp();

        // o = attn @ v (v in regs, already pixel-paired)
        ull ov[2][4];
        {
            const int h = ln >> 3;
            ull a2[2][4];
#pragma unroll
            for (int pr = 0; pr < 2; ++pr)
#pragma unroll
                for (int j = 0; j < 4; ++j)
                    a2[pr][j] = pk2(sa[pr * 2][h * 4 + j], sa[pr * 2 + 1][h * 4 + j]);
#pragma unroll
            for (int pr = 0; pr < 2; ++pr)
#pragma unroll
                for (int i = 0; i < 4; ++i) {
                    ull acc = mul2(a2[pr][0], va[0][pr][i]);
                    acc = fma2(a2[pr][1], va[1][pr][i], acc);
                    acc = fma2(a2[pr][2], va[2][pr][i], acc);
                    ov[pr][i] = fma2(a2[pr][3], va[3][pr][i], acc);
                }
        }
        __syncwarp();
#pragma unroll
        for (int pr = 0; pr < 2; ++pr)
#pragma unroll
            for (int i = 0; i < 4; ++i) stp(sx, (o4 + i) * 2 + pr, ov[pr][i]);
        __syncwarp();

        // x += o @ o_w + o_b
        ull oa[2][4];
        {
            float4 ob = ldg4(o_b + l * 128 + o4);
            oa[0][0] = oa[1][0] = dup2(ob.x); oa[0][1] = oa[1][1] = dup2(ob.y);
            oa[0][2] = oa[1][2] = dup2(ob.z); oa[0][3] = oa[1][3] = dup2(ob.w);
        }
        mv2<128, 1, 1, 128>(oW, sx, 0, o4, &oa[0][0]);
#pragma unroll
        for (int pr = 0; pr < 2; ++pr)
#pragma unroll
            for (int i = 0; i < 4; ++i) x2[pr][i] = add2(x2[pr][i], oa[pr][i]);

        // ---- MLP
        ln2(x2[0], 1e-6f, t2[0]);
        ln2(x2[1], 1e-6f, t2[1]);
        __syncwarp();   // o-proj reads of sx done
#pragma unroll
        for (int pr = 0; pr < 2; ++pr)
#pragma unroll
            for (int i = 0; i < 4; ++i) stp(sx, (o4 + i) * 2 + pr, t2[pr][i]);
        __syncwarp();

        ull f1[2][16];
        {
#pragma unroll
            for (int r = 0; r < 4; ++r) {
                float4 fb = ldg4(fc1_b + l * 512 + r * 128 + o4);
                f1[0][r * 4 + 0] = f1[1][r * 4 + 0] = dup2(fb.x);
                f1[0][r * 4 + 1] = f1[1][r * 4 + 1] = dup2(fb.y);
                f1[0][r * 4 + 2] = f1[1][r * 4 + 2] = dup2(fb.z);
                f1[0][r * 4 + 3] = f1[1][r * 4 + 3] = dup2(fb.w);
            }
        }
        mv2<128, 1, 4, 512>(f1W, sx, 0, o4, &f1[0][0]);
        __syncwarp();   // attention reads of sk long done; safe to overwrite
#pragma unroll
        for (int r = 0; r < 4; ++r)
#pragma unroll
            for (int i = 0; i < 4; ++i) {
                int hidx = r * 128 + o4 + i;     // 0..511
                stp(sk, hidx * 2 + 0, gelu_t2(f1[0][r * 4 + i]));
                stp(sk, hidx * 2 + 1, gelu_t2(f1[1][r * 4 + i]));
            }
        __syncwarp();

        ull fa[2][4];
        {
            float4 fb = ldg4(fc2_b + l * 128 + o4);
            fa[0][0] = fa[1][0] = dup2(fb.x); fa[0][1] = fa[1][1] = dup2(fb.y);
            fa[0][2] = fa[1][2] = dup2(fb.z); fa[0][3] = fa[1][3] = dup2(fb.w);
        }
        mv2<512, 1, 1, 128>(f2W, sk, 0, o4, &fa[0][0]);
#pragma unroll
        for (int pr = 0; pr < 2; ++pr)
#pragma unroll
            for (int i = 0; i < 4; ++i) x2[pr][i] = add2(x2[pr][i], fa[pr][i]);
    }

    // ---- final head: 3 column passes over WA/WB keep accumulators small
    {
        ull xf[2][4];
        ln2(x2[0], 1e-6f, xf[0]);
        ln2(x2[1], 1e-6f, xf[1]);
        __syncwarp();
#pragma unroll
        for (int pr = 0; pr < 2; ++pr)
#pragma unroll
            for (int i = 0; i < 4; ++i) stp(sx, (o4 + i) * 2 + pr, xf[pr][i]);
#pragma unroll 1
        for (int j = 0; j < 4; ++j) {
            ull cv[2][4], cf[2][4];
            loadctx(j, cv);
            ln2(cv[0], 1e-6f, cf[0]);
            ln2(cv[1], 1e-6f, cf[1]);
#pragma unroll
            for (int pr = 0; pr < 2; ++pr)
#pragma unroll
                for (int i = 0; i < 4; ++i) stp(sc + j * 512, (o4 + i) * 2 + pr, cf[pr][i]);
        }
        __syncwarp();

        ull s2[4][2];
#pragma unroll
        for (int j = 0; j < 4; ++j) { s2[j][0] = pk2(0.f, 0.f); s2[j][1] = pk2(0.f, 0.f); }

#pragma unroll 1
        for (int r = 0; r < 3; ++r) {
            ull tbs[2][4];
            {
                float4 ob = ldg4(out1_b + r * 128 + o4);
                tbs[0][0] = tbs[1][0] = dup2(ob.x); tbs[0][1] = tbs[1][1] = dup2(ob.y);
                tbs[0][2] = tbs[1][2] = dup2(ob.z); tbs[0][3] = tbs[1][3] = dup2(ob.w);
            }
            mv2<128, 1, 1, 384>(g_WA + r * 128, sx, 0, o4, &tbs[0][0]);

            ull us[4][2][4];
#pragma unroll
            for (int j = 0; j < 4; ++j)
#pragma unroll
                for (int pr = 0; pr < 2; ++pr)
#pragma unroll
                    for (int i = 0; i < 4; ++i) us[j][pr][i] = pk2(0.f, 0.f);
            mv2<128, 4, 1, 384>(g_WB + r * 128, sc, 512, o4, &us[0][0][0]);

            float4 w2v = ldg4(out2_w + r * 128 + o4);
            ull wd[4] = {dup2(w2v.x), dup2(w2v.y), dup2(w2v.z), dup2(w2v.w)};
#pragma unroll
            for (int j = 0; j < 4; ++j)
#pragma unroll
                for (int pr = 0; pr < 2; ++pr)
#pragma unroll
                    for (int i = 0; i < 4; ++i)
                        s2[j][pr] = fma2(gelu_e2(add2(tbs[pr][i], us[j][pr][i])), wd[i], s2[j][pr]);
        }

        const float o2b = __ldg(out2_b);
#pragma unroll
        for (int j = 0; j < 4; ++j)
#pragma unroll
            for (int pr = 0; pr < 2; ++pr) {
                ull t = wsum2(s2[j][pr]);
                float a, bv; up2(t, a, bv);
                if (ln == 0) {
                    sa[pr * 2][j] = a + o2b;
                    sa[pr * 2 + 1][j] = bv + o2b;
                }
            }
        __syncwarp();

        if (ln < 16) {
            int p = ln >> 2, j = ln & 3;
            float l0 = sa[p][0], l1 = sa[p][1], l2 = sa[p][2], l3 = sa[p][3];
            float mx = fmaxf(fmaxf(l0, l1), fmaxf(l2, l3));
            float den = expf(l0 - mx) + expf(l1 - mx) + expf(l2 - mx) + expf(l3 - mx);
            float e = expf(sa[p][j] - mx);
            out[(((size_t)b * 4 + j) * kHu + hu) * kWu + wu0 + p] = e / den;
        }
    }
}

extern "C" void kernel_launch(void* const* d_in, const int* in_sizes, int n_in,
                              void* d_out, int out_size) {
    const float* feat     = (const float*)d_in[0];
    const float* featup   = (const float*)d_in[1];
    const float* ctx_ln_b = (const float*)d_in[2];
    const float* q_w      = (const float*)d_in[3];
    const float* q_b      = (const float*)d_in[4];
    const float* k_w      = (const float*)d_in[5];
    const float* k_b      = (const float*)d_in[6];
    const float* v_w      = (const float*)d_in[7];
    const float* v_b      = (const float*)d_in[8];
    const float* o_w      = (const float*)d_in[9];
    const float* o_b      = (const float*)d_in[10];
    const float* fc1_w    = (const float*)d_in[11];
    const float* fc1_b    = (const float*)d_in[12];
    const float* fc2_w    = (const float*)d_in[13];
    const float* fc2_b    = (const float*)d_in[14];
    const float* out1_w   = (const float*)d_in[15];
    const float* out1_b   = (const float*)d_in[16];
    const float* out2_w   = (const float*)d_in[17];
    const float* out2_b   = (const float*)d_in[18];
    const float* ctx_ln_g = (const float*)d_in[19];

    prep_kernel<<<(128 * 384 + 255) / 256, 256>>>(out1_w);
    upsample_tf_kernel<<<kN / 8, 64>>>(
        feat, featup, ctx_ln_b, q_w, q_b, k_w, k_b, v_w, v_b, o_w, o_b,
        fc1_w, fc1_b, fc2_w, fc2_b, out1_b, out2_w, out2_b, ctx_ln_g,
        (float*)d_out);
}

// round 5
// speedup vs baseline: 1.7487x; 1.3524x over previous
#include <cuda_runtime.h>
#include <math.h>

typedef unsigned long long ull;

namespace {
constexpr int kB = 2, kC = 128, kHd = 64, kWd = 96, kHu = 128, kWu = 192;
constexpr int kN = kB * kHu * kWu;
constexpr int kHWd = kHd * kWd, kHWu = kHu * kWu;
}

// Precombined final-head weights: fin=[xf,cf,xf-cf] => fin@W = xf@(W0+W2) + cf@(W1-W2)
__device__ float g_WA[128 * 384];
__device__ float g_WB[128 * 384];

__global__ void prep_kernel(const float* __restrict__ o1w) {
    int i = blockIdx.x * blockDim.x + threadIdx.x;
    if (i < 128 * 384) {
        int in = i / 384, o = i - in * 384;
        float w2 = o1w[(256 + in) * 384 + o];
        g_WA[i] = o1w[in * 384 + o] + w2;
        g_WB[i] = o1w[(128 + in) * 384 + o] - w2;
    }
}

// ---- packed f32x2 helpers (SASS FFMA2 path, PTX-only) ----
__device__ __forceinline__ ull pk2(float a, float b) {
    ull r; asm("mov.b64 %0,{%1,%2};" : "=l"(r) : "f"(a), "f"(b)); return r;
}
__device__ __forceinline__ ull dup2(float a) { return pk2(a, a); }
__device__ __forceinline__ void up2(ull v, float& a, float& b) {
    asm("mov.b64 {%0,%1},%2;" : "=f"(a), "=f"(b) : "l"(v));
}
__device__ __forceinline__ ull fma2(ull a, ull b, ull c) {
    ull d; asm("fma.rn.f32x2 %0,%1,%2,%3;" : "=l"(d) : "l"(a), "l"(b), "l"(c)); return d;
}
__device__ __forceinline__ ull add2(ull a, ull b) {
    ull d; asm("add.rn.f32x2 %0,%1,%2;" : "=l"(d) : "l"(a), "l"(b)); return d;
}
__device__ __forceinline__ ull mul2(ull a, ull b) {
    ull d; asm("mul.rn.f32x2 %0,%1,%2;" : "=l"(d) : "l"(a), "l"(b)); return d;
}

// pixel-pair-interleaved smem with XOR bank swizzle; slot f2 -> float offset 2*swz(f2)
__device__ __forceinline__ int swzi(int f2) { return f2 ^ ((f2 >> 4) & 15); }
__device__ __forceinline__ ull ldp(const float* b, int f2) {
    return *reinterpret_cast<const ull*>(b + 2 * swzi(f2));
}
__device__ __forceinline__ void stp(float* b, int f2, ull v) {
    *reinterpret_cast<ull*>(b + 2 * swzi(f2)) = v;
}

__device__ __forceinline__ ull wsum2(ull v) {
#pragma unroll
    for (int o = 16; o; o >>= 1) v = add2(v, __shfl_xor_sync(0xffffffffu, v, o));
    return v;
}

// LayerNorm of one pixel-pair: v[i] packs channel (o4+i) of two pixels
__device__ __forceinline__ void ln2(const ull v[4], float eps, ull o[4]) {
    ull s = add2(add2(v[0], v[1]), add2(v[2], v[3]));
    ull q = fma2(v[0], v[0], fma2(v[1], v[1], fma2(v[2], v[2], mul2(v[3], v[3]))));
    s = wsum2(s); q = wsum2(q);
    float s0, s1, q0, q1; up2(s, s0, s1); up2(q, q0, q1);
    float m0 = s0 * (1.0f / 128.0f), m1 = s1 * (1.0f / 128.0f);
    float r0 = rsqrtf(fmaxf(q0 * (1.0f / 128.0f) - m0 * m0, 0.0f) + eps);
    float r1 = rsqrtf(fmaxf(q1 * (1.0f / 128.0f) - m1 * m1, 0.0f) + eps);
    ull nm = pk2(-m0, -m1), rr = pk2(r0, r1);
#pragma unroll
    for (int i = 0; i < 4; ++i) o[i] = mul2(add2(v[i], nm), rr);
}

__device__ __forceinline__ float gelu_t(float x) {
    float u = 0.7978845608028654f * (x + 0.044715f * x * x * x);
    return 0.5f * x * (1.0f + tanhf(u));
}
__device__ __forceinline__ ull gelu_t2(ull v) { float a, b; up2(v, a, b); return pk2(gelu_t(a), gelu_t(b)); }
__device__ __forceinline__ float gelu_e(float x) { return 0.5f * x * (1.0f + erff(x * 0.7071067811865475f)); }
__device__ __forceinline__ ull gelu_e2(ull v) { float a, b; up2(v, a, b); return pk2(gelu_e(a), gelu_e(b)); }

__device__ __forceinline__ float4 ldg4(const float* p) {
    return __ldg(reinterpret_cast<const float4*>(p));
}

// Packed multi-row GEMV: acc[row*8 + pair*4 + i] (NG=1) or acc[row*(2*NG*4)+...]
template <int NIN, int ROWS, int NG, int STRIDE>
__device__ __forceinline__ void mv2(const float* __restrict__ W, const float* __restrict__ act,
                                    int actStride, int o4, ull* acc) {
#pragma unroll 2
    for (int in = 0; in < NIN; ++in) {
        ull wd[NG][4];
#pragma unroll
        for (int r = 0; r < NG; ++r) {
            float4 wv = ldg4(W + in * STRIDE + r * 128 + o4);
            wd[r][0] = dup2(wv.x); wd[r][1] = dup2(wv.y);
            wd[r][2] = dup2(wv.z); wd[r][3] = dup2(wv.w);
        }
#pragma unroll
        for (int row = 0; row < ROWS; ++row) {
            ull a0 = ldp(act + row * actStride, in * 2 + 0);
            ull a1 = ldp(act + row * actStride, in * 2 + 1);
            ull* ar = acc + row * (2 * NG * 4);
#pragma unroll
            for (int r = 0; r < NG; ++r)
#pragma unroll
                for (int i = 0; i < 4; ++i) {
                    ar[r * 4 + i]          = fma2(a0, wd[r][i], ar[r * 4 + i]);
                    ar[NG * 4 + r * 4 + i] = fma2(a1, wd[r][i], ar[NG * 4 + r * 4 + i]);
                }
        }
    }
}

__global__ __launch_bounds__(64, 8)
void upsample_tf_kernel(
    const float* __restrict__ feat, const float* __restrict__ featup,
    const float* __restrict__ ctx_ln_b,
    const float* __restrict__ q_w, const float* __restrict__ q_b,
    const float* __restrict__ k_w, const float* __restrict__ k_b,
    const float* __restrict__ v_w, const float* __restrict__ v_b,
    const float* __restrict__ o_w, const float* __restrict__ o_b,
    const float* __restrict__ fc1_w, const float* __restrict__ fc1_b,
    const float* __restrict__ fc2_w, const float* __restrict__ fc2_b,
    const float* __restrict__ out1_b,
    const float* __restrict__ out2_w, const float* __restrict__ out2_b,
    const float* __restrict__ ctx_ln_g,
    float* __restrict__ out)
{
    // paired layout: 128-ch vector = 512 floats. s_c also serves as fc1-hidden (2048 floats).
    __shared__ __align__(16) float s_x[2][512];       // xn/ov/hn/xf
    __shared__ __align__(16) float s_c[2][4][512];    // cn / fc1 hidden / cf
    __shared__ __align__(16) float s_a[2][4][16];     // final logits staging

    const int w = threadIdx.x >> 5, ln = threadIdx.x & 31, o4 = ln * 4;
    const int g = blockIdx.x * 2 + w;
    const int n0 = g * 4;
    if (n0 >= kN) return;
    const int b = n0 / kHWu;
    const int rr = n0 - b * kHWu;
    const int hu = rr / kWu, wu0 = rr - hu * kWu;

    float* sx = s_x[w];
    float* sc = &s_c[w][0][0];
    float (*sa)[16] = s_a[w];

    const int rh0 = min(hu >> 1, kHd - 1), rh1 = min((hu >> 1) + 1, kHd - 1);
    const int hd = ln >> 3;                            // this lane's attention head
    const float slope = exp2f(-(float)(hd + 1) * 1.1462406251802891f); // log2(24)/4

    // ---- x load
    ull x2[2][4];
    {
        const float* fu = featup + ((size_t)b * kC) * kHWu + (size_t)hu * kWu + wu0;
#pragma unroll
        for (int i = 0; i < 4; ++i) {
            float4 p = ldg4(fu + (size_t)(o4 + i) * kHWu);
            x2[0][i] = pk2(p.x, p.y);
            x2[1][i] = pk2(p.z, p.w);
        }
    }

    auto loadctx = [&](int j, ull cv[2][4]) {
        const int ky = j >> 1, kx = j & 1;
        const int rhv = ky ? rh1 : rh0;
        const float* fm = feat + ((size_t)b * kC) * kHWd + rhv * kWd;
#pragma unroll
        for (int i = 0; i < 4; ++i) {
            const float* cp = fm + (size_t)(o4 + i) * kHWd;
            float v0 = __ldg(cp + min(((wu0 + 0) >> 1) + kx, kWd - 1));
            float v1 = __ldg(cp + min(((wu0 + 1) >> 1) + kx, kWd - 1));
            float v2 = __ldg(cp + min(((wu0 + 2) >> 1) + kx, kWd - 1));
            float v3 = __ldg(cp + min(((wu0 + 3) >> 1) + kx, kWd - 1));
            cv[0][i] = pk2(v0, v1);
            cv[1][i] = pk2(v2, v3);
        }
    };

#pragma unroll 1
    for (int l = 0; l < 2; ++l) {
        const float* qW  = q_w  + l * 16384;
        const float* kW  = k_w  + l * 16384;
        const float* vW  = v_w  + l * 16384;
        const float* oW  = o_w  + l * 16384;
        const float* f1W = fc1_w + l * 65536;
        const float* f2W = fc2_w + l * 65536;

        // xn = LN(x) -> sx
        ull t2[2][4];
        ln2(x2[0], 1e-6f, t2[0]);
        ln2(x2[1], 1e-6f, t2[1]);
        __syncwarp();
#pragma unroll
        for (int pr = 0; pr < 2; ++pr)
#pragma unroll
            for (int i = 0; i < 4; ++i) stp(sx, (o4 + i) * 2 + pr, t2[pr][i]);

        // cn = LN(ctx,1e-5)*g + b -> sc
        {
            float4 gg = ldg4(ctx_ln_g + l * 128 + o4);
            float4 bb = ldg4(ctx_ln_b + l * 128 + o4);
            ull gd[4] = {dup2(gg.x), dup2(gg.y), dup2(gg.z), dup2(gg.w)};
            ull bd[4] = {dup2(bb.x), dup2(bb.y), dup2(bb.z), dup2(bb.w)};
#pragma unroll 1
            for (int j = 0; j < 4; ++j) {
                ull cv[2][4], cn[2][4];
                loadctx(j, cv);
                ln2(cv[0], 1e-5f, cn[0]);
                ln2(cv[1], 1e-5f, cn[1]);
#pragma unroll
                for (int pr = 0; pr < 2; ++pr)
#pragma unroll
                    for (int i = 0; i < 4; ++i)
                        stp(sc + j * 512, (o4 + i) * 2 + pr, fma2(cn[pr][i], gd[i], bd[i]));
            }
        }
        __syncwarp();

        // q = xn @ q_w + q_b   (stays in regs)
        ull qa[2][4];
        {
            float4 qb = ldg4(q_b + l * 128 + o4);
            qa[0][0] = qa[1][0] = dup2(qb.x); qa[0][1] = qa[1][1] = dup2(qb.y);
            qa[0][2] = qa[1][2] = dup2(qb.z); qa[0][3] = qa[1][3] = dup2(qb.w);
        }
        mv2<128, 1, 1, 128>(qW, sx, 0, o4, &qa[0][0]);

        // ---- k in 2-row passes; fold each row straight into partial scores
        ull sc2[4][2];   // raw q.k score per key j, pixel-paired
        {
            float4 kb = ldg4(k_b + l * 128 + o4);
            ull kb2[4] = {dup2(kb.x), dup2(kb.y), dup2(kb.z), dup2(kb.w)};
#pragma unroll 1
            for (int jp = 0; jp < 2; ++jp) {
                ull ka[16];
#pragma unroll
                for (int row = 0; row < 2; ++row)
#pragma unroll
                    for (int pr = 0; pr < 2; ++pr)
#pragma unroll
                        for (int i = 0; i < 4; ++i) ka[row * 8 + pr * 4 + i] = kb2[i];
                mv2<128, 2, 1, 128>(kW, sc + jp * 1024, 512, o4, ka);
#pragma unroll
                for (int row = 0; row < 2; ++row)
#pragma unroll
                    for (int pr = 0; pr < 2; ++pr) {
                        ull p = mul2(qa[pr][0], ka[row * 8 + pr * 4 + 0]);
                        p = fma2(qa[pr][1], ka[row * 8 + pr * 4 + 1], p);
                        p = fma2(qa[pr][2], ka[row * 8 + pr * 4 + 2], p);
                        p = fma2(qa[pr][3], ka[row * 8 + pr * 4 + 3], p);
                        // reduce over the 8 lanes of this head group
                        p = add2(p, __shfl_xor_sync(0xffffffffu, p, 1));
                        p = add2(p, __shfl_xor_sync(0xffffffffu, p, 2));
                        p = add2(p, __shfl_xor_sync(0xffffffffu, p, 4));
                        sc2[jp * 2 + row][pr] = p;
                    }
            }
        }

        // ---- softmax with ALiBi bias, per pixel, redundantly in every lane
        ull a2[4][2];  // attn weight per key, pixel-paired
        {
#pragma unroll
            for (int pr = 0; pr < 2; ++pr) {
                float sj[2][4];  // [pixel-in-pair][key]
#pragma unroll
                for (int j = 0; j < 4; ++j) {
                    float pa, pb; up2(sc2[j][pr], pa, pb);
                    const int ky = j >> 1, kx = j & 1;
                    const int rhv = ky ? rh1 : rh0;
#pragma unroll
                    for (int t = 0; t < 2; ++t) {
                        int wup = wu0 + pr * 2 + t;
                        int rwv = min((wup >> 1) + kx, kWd - 1);
                        float cd = -(float)(abs(hu - 2 * rhv) + abs(wup - 2 * rwv));
                        sj[t][j] = (t ? pb : pa) * 0.17677669529663687f + slope * cd;
                    }
                }
                float av[2][4];
#pragma unroll
                for (int t = 0; t < 2; ++t) {
                    float mx = fmaxf(fmaxf(sj[t][0], sj[t][1]), fmaxf(sj[t][2], sj[t][3]));
                    float e0 = expf(sj[t][0] - mx), e1 = expf(sj[t][1] - mx);
                    float e2 = expf(sj[t][2] - mx), e3 = expf(sj[t][3] - mx);
                    float inv = 1.0f / (e0 + e1 + e2 + e3);
                    av[t][0] = e0 * inv; av[t][1] = e1 * inv;
                    av[t][2] = e2 * inv; av[t][3] = e3 * inv;
                }
#pragma unroll
                for (int j = 0; j < 4; ++j) a2[j][pr] = pk2(av[0][j], av[1][j]);
            }
        }

        // ---- v in 2-row passes, folded immediately into o accumulator
        ull ov[2][4];
        {
            float4 vb = ldg4(v_b + l * 128 + o4);
            ull vb2[4] = {dup2(vb.x), dup2(vb.y), dup2(vb.z), dup2(vb.w)};
#pragma unroll
            for (int pr = 0; pr < 2; ++pr)
#pragma unroll
                for (int i = 0; i < 4; ++i) ov[pr][i] = pk2(0.f, 0.f);
#pragma unroll 1
            for (int jp = 0; jp < 2; ++jp) {
                ull va[16];
#pragma unroll
                for (int row = 0; row < 2; ++row)
#pragma unroll
                    for (int pr = 0; pr < 2; ++pr)
#pragma unroll
                        for (int i = 0; i < 4; ++i) va[row * 8 + pr * 4 + i] = vb2[i];
                mv2<128, 2, 1, 128>(vW, sc + jp * 1024, 512, o4, va);
#pragma unroll
                for (int row = 0; row < 2; ++row)
#pragma unroll
                    for (int pr = 0; pr < 2; ++pr)
#pragma unroll
                        for (int i = 0; i < 4; ++i)
                            ov[pr][i] = fma2(a2[jp * 2 + row][pr], va[row * 8 + pr * 4 + i], ov[pr][i]);
            }
        }
        __syncwarp();   // q-pass reads of sx done
#pragma unroll
        for (int pr = 0; pr < 2; ++pr)
#pragma unroll
            for (int i = 0; i < 4; ++i) stp(sx, (o4 + i) * 2 + pr, ov[pr][i]);
        __syncwarp();

        // x += o @ o_w + o_b
        {
            ull oa[2][4];
            float4 ob = ldg4(o_b + l * 128 + o4);
            oa[0][0] = oa[1][0] = dup2(ob.x); oa[0][1] = oa[1][1] = dup2(ob.y);
            oa[0][2] = oa[1][2] = dup2(ob.z); oa[0][3] = oa[1][3] = dup2(ob.w);
            mv2<128, 1, 1, 128>(oW, sx, 0, o4, &oa[0][0]);
#pragma unroll
            for (int pr = 0; pr < 2; ++pr)
#pragma unroll
                for (int i = 0; i < 4; ++i) x2[pr][i] = add2(x2[pr][i], oa[pr][i]);
        }

        // ---- MLP: hn -> sx ; hidden -> sc (cn dead)
        ln2(x2[0], 1e-6f, t2[0]);
        ln2(x2[1], 1e-6f, t2[1]);
        __syncwarp();
#pragma unroll
        for (int pr = 0; pr < 2; ++pr)
#pragma unroll
            for (int i = 0; i < 4; ++i) stp(sx, (o4 + i) * 2 + pr, t2[pr][i]);
        __syncwarp();

#pragma unroll 1
        for (int p = 0; p < 2; ++p) {   // fc1 output cols p*256 .. p*256+255
            ull f1[16];
#pragma unroll
            for (int r = 0; r < 2; ++r) {
                float4 fb = ldg4(fc1_b + l * 512 + p * 256 + r * 128 + o4);
                f1[r * 4 + 0] = f1[8 + r * 4 + 0] = dup2(fb.x);
                f1[r * 4 + 1] = f1[8 + r * 4 + 1] = dup2(fb.y);
                f1[r * 4 + 2] = f1[8 + r * 4 + 2] = dup2(fb.z);
                f1[r * 4 + 3] = f1[8 + r * 4 + 3] = dup2(fb.w);
            }
            mv2<128, 1, 2, 512>(f1W + p * 256, sx, 0, o4, f1);
#pragma unroll
            for (int r = 0; r < 2; ++r)
#pragma unroll
                for (int i = 0; i < 4; ++i) {
                    int hidx = p * 256 + r * 128 + o4 + i;   // 0..511
                    stp(sc, hidx * 2 + 0, gelu_t2(f1[r * 4 + i]));
                    stp(sc, hidx * 2 + 1, gelu_t2(f1[8 + r * 4 + i]));
                }
        }
        __syncwarp();

        {
            ull fa[2][4];
            float4 fb = ldg4(fc2_b + l * 128 + o4);
            fa[0][0] = fa[1][0] = dup2(fb.x); fa[0][1] = fa[1][1] = dup2(fb.y);
            fa[0][2] = fa[1][2] = dup2(fb.z); fa[0][3] = fa[1][3] = dup2(fb.w);
            mv2<512, 1, 1, 128>(f2W, sc, 0, o4, &fa[0][0]);
#pragma unroll
            for (int pr = 0; pr < 2; ++pr)
#pragma unroll
                for (int i = 0; i < 4; ++i) x2[pr][i] = add2(x2[pr][i], fa[pr][i]);
        }
        __syncwarp();   // fc2 reads of sc done before next-layer cn overwrite
    }

    // ---- final head
    {
        ull xf[2][4];
        ln2(x2[0], 1e-6f, xf[0]);
        ln2(x2[1], 1e-6f, xf[1]);
        __syncwarp();
#pragma unroll
        for (int pr = 0; pr < 2; ++pr)
#pragma unroll
            for (int i = 0; i < 4; ++i) stp(sx, (o4 + i) * 2 + pr, xf[pr][i]);
#pragma unroll 1
        for (int j = 0; j < 4; ++j) {
            ull cv[2][4], cf[2][4];
            loadctx(j, cv);
            ln2(cv[0], 1e-6f, cf[0]);
            ln2(cv[1], 1e-6f, cf[1]);
#pragma unroll
            for (int pr = 0; pr < 2; ++pr)
#pragma unroll
                for (int i = 0; i < 4; ++i) stp(sc + j * 512, (o4 + i) * 2 + pr, cf[pr][i]);
        }
        __syncwarp();

        ull s2[4][2];
#pragma unroll
        for (int j = 0; j < 4; ++j) { s2[j][0] = pk2(0.f, 0.f); s2[j][1] = pk2(0.f, 0.f); }

#pragma unroll 1
        for (int r = 0; r < 3; ++r) {
            ull tbs[2][4];
            {
                float4 ob = ldg4(out1_b + r * 128 + o4);
                tbs[0][0] = tbs[1][0] = dup2(ob.x); tbs[0][1] = tbs[1][1] = dup2(ob.y);
                tbs[0][2] = tbs[1][2] = dup2(ob.z); tbs[0][3] = tbs[1][3] = dup2(ob.w);
            }
            mv2<128, 1, 1, 384>(g_WA + r * 128, sx, 0, o4, &tbs[0][0]);

            float4 w2v = ldg4(out2_w + r * 128 + o4);
            ull wd[4] = {dup2(w2v.x), dup2(w2v.y), dup2(w2v.z), dup2(w2v.w)};

#pragma unroll 1
            for (int jp = 0; jp < 2; ++jp) {
                ull us[16];
#pragma unroll
                for (int t = 0; t < 16; ++t) us[t] = pk2(0.f, 0.f);
                mv2<128, 2, 1, 384>(g_WB + r * 128, sc + jp * 1024, 512, o4, us);
#pragma unroll
                for (int row = 0; row < 2; ++row)
#pragma unroll
                    for (int pr = 0; pr < 2; ++pr)
#pragma unroll
                        for (int i = 0; i < 4; ++i)
                            s2[jp * 2 + row][pr] = fma2(gelu_e2(add2(tbs[pr][i], us[row * 8 + pr * 4 + i])),
                                                        wd[i], s2[jp * 2 + row][pr]);
            }
        }

        const float o2b = __ldg(out2_b);
#pragma unroll
        for (int j = 0; j < 4; ++j)
#pragma unroll
            for (int pr = 0; pr < 2; ++pr) {
                ull t = wsum2(s2[j][pr]);
                float a, bv; up2(t, a, bv);
                if (ln == 0) {
                    sa[pr * 2][j] = a + o2b;
                    sa[pr * 2 + 1][j] = bv + o2b;
                }
            }
        __syncwarp();

        if (ln < 16) {
            int p = ln >> 2, j = ln & 3;
            float l0 = sa[p][0], l1 = sa[p][1], l2 = sa[p][2], l3 = sa[p][3];
            float mx = fmaxf(fmaxf(l0, l1), fmaxf(l2, l3));
            float den = expf(l0 - mx) + expf(l1 - mx) + expf(l2 - mx) + expf(l3 - mx);
            float e = expf(sa[p][j] - mx);
            out[(((size_t)b * 4 + j) * kHu + hu) * kWu + wu0 + p] = e / den;
        }
    }
}

extern "C" void kernel_launch(void* const* d_in, const int* in_sizes, int n_in,
                              void* d_out, int out_size) {
    const float* feat     = (const float*)d_in[0];
    const float* featup   = (const float*)d_in[1];
    const float* ctx_ln_b = (const float*)d_in[2];
    const float* q_w      = (const float*)d_in[3];
    const float* q_b      = (const float*)d_in[4];
    const float* k_w      = (const float*)d_in[5];
    const float* k_b      = (const float*)d_in[6];
    const float* v_w      = (const float*)d_in[7];
    const float* v_b      = (const float*)d_in[8];
    const float* o_w      = (const float*)d_in[9];
    const float* o_b      = (const float*)d_in[10];
    const float* fc1_w    = (const float*)d_in[11];
    const float* fc1_b    = (const float*)d_in[12];
    const float* fc2_w    = (const float*)d_in[13];
    const float* fc2_b    = (const float*)d_in[14];
    const float* out1_w   = (const float*)d_in[15];
    const float* out1_b   = (const float*)d_in[16];
    const float* out2_w   = (const float*)d_in[17];
    const float* out2_b   = (const float*)d_in[18];
    const float* ctx_ln_g = (const float*)d_in[19];

    prep_kernel<<<(128 * 384 + 255) / 256, 256>>>(out1_w);
    upsample_tf_kernel<<<kN / 8, 64>>>(
        feat, featup, ctx_ln_b, q_w, q_b, k_w, k_b, v_w, v_b, o_w, o_b,
        fc1_w, fc1_b, fc2_w, fc2_b, out1_b, out2_w, out2_b, ctx_ln_g,
        (float*)d_out);
}

// round 6
// speedup vs baseline: 1.9687x; 1.1258x over previous
#include <cuda_runtime.h>
#include <math.h>

typedef unsigned long long ull;

namespace {
constexpr int kB = 2, kC = 128, kHd = 64, kWd = 96, kHu = 128, kWu = 192;
constexpr int kN = kB * kHu * kWu;
constexpr int kHWd = kHd * kWd, kHWu = kHu * kWu;
}

// Precombined final-head weights: fin=[xf,cf,xf-cf] => fin@W = xf@(W0+W2) + cf@(W1-W2)
__device__ float g_WA[128 * 384];
__device__ float g_WB[128 * 384];

__global__ void prep_kernel(const float* __restrict__ o1w) {
    int i = blockIdx.x * blockDim.x + threadIdx.x;
    if (i < 128 * 384) {
        int in = i / 384, o = i - in * 384;
        float w2 = o1w[(256 + in) * 384 + o];
        g_WA[i] = o1w[in * 384 + o] + w2;
        g_WB[i] = o1w[(128 + in) * 384 + o] - w2;
    }
}

// ---- packed f32x2 helpers (SASS FFMA2 path, PTX-only) ----
__device__ __forceinline__ ull pk2(float a, float b) {
    ull r; asm("mov.b64 %0,{%1,%2};" : "=l"(r) : "f"(a), "f"(b)); return r;
}
__device__ __forceinline__ ull dup2(float a) { return pk2(a, a); }
__device__ __forceinline__ void up2(ull v, float& a, float& b) {
    asm("mov.b64 {%0,%1},%2;" : "=f"(a), "=f"(b) : "l"(v));
}
__device__ __forceinline__ ull fma2(ull a, ull b, ull c) {
    ull d; asm("fma.rn.f32x2 %0,%1,%2,%3;" : "=l"(d) : "l"(a), "l"(b), "l"(c)); return d;
}
__device__ __forceinline__ ull add2(ull a, ull b) {
    ull d; asm("add.rn.f32x2 %0,%1,%2;" : "=l"(d) : "l"(a), "l"(b)); return d;
}
__device__ __forceinline__ ull mul2(ull a, ull b) {
    ull d; asm("mul.rn.f32x2 %0,%1,%2;" : "=l"(d) : "l"(a), "l"(b)); return d;
}

// paired smem (4B per (ch,pixel), pixel-pair packed) with XOR swizzle
__device__ __forceinline__ int swzi(int f2) { return f2 ^ ((f2 >> 4) & 15); }
__device__ __forceinline__ ull ldp(const float* b, int f2) {
    return *reinterpret_cast<const ull*>(b + 2 * swzi(f2));
}
__device__ __forceinline__ void stp(float* b, int f2, ull v) {
    *reinterpret_cast<ull*>(b + 2 * swzi(f2)) = v;
}

// dup'd smem (8B per (ch,pixel), scalar stored twice). slot s = ch*4+px.
__device__ __forceinline__ ull ldd(const float* b, int s) {
    int sw = s ^ ((s >> 4) & 15);
    return *reinterpret_cast<const ull*>(b + 2 * sw);
}
__device__ __forceinline__ void sdd(float* b, int s, float v) {
    int sw = s ^ ((s >> 4) & 15);
    b[2 * sw] = v; b[2 * sw + 1] = v;
}

__device__ __forceinline__ ull wsum2(ull v) {
#pragma unroll
    for (int o = 16; o; o >>= 1) v = add2(v, __shfl_xor_sync(0xffffffffu, v, o));
    return v;
}

// pixel-paired LayerNorm (for ctx rows): v[i] packs channel (o4+i) of two pixels
__device__ __forceinline__ void ln2(const ull v[4], float eps, ull o[4]) {
    ull s = add2(add2(v[0], v[1]), add2(v[2], v[3]));
    ull q = fma2(v[0], v[0], fma2(v[1], v[1], fma2(v[2], v[2], mul2(v[3], v[3]))));
    s = wsum2(s); q = wsum2(q);
    float s0, s1, q0, q1; up2(s, s0, s1); up2(q, q0, q1);
    float m0 = s0 * (1.0f / 128.0f), m1 = s1 * (1.0f / 128.0f);
    float r0 = rsqrtf(fmaxf(q0 * (1.0f / 128.0f) - m0 * m0, 0.0f) + eps);
    float r1 = rsqrtf(fmaxf(q1 * (1.0f / 128.0f) - m1 * m1, 0.0f) + eps);
    ull nm = pk2(-m0, -m1), rr = pk2(r0, r1);
#pragma unroll
    for (int i = 0; i < 4; ++i) o[i] = mul2(add2(v[i], nm), rr);
}

// channel-paired per-pixel LayerNorm: v[px][cp] packs channels (o4+2cp, o4+2cp+1)
__device__ __forceinline__ void lnP(const ull v[4][2], float eps, ull o[4][2]) {
#pragma unroll
    for (int px = 0; px < 4; ++px) {
        ull s2 = add2(v[px][0], v[px][1]);
        ull q2 = fma2(v[px][0], v[px][0], mul2(v[px][1], v[px][1]));
        float sa, sb, qa, qb; up2(s2, sa, sb); up2(q2, qa, qb);
        ull t = wsum2(pk2(sa + sb, qa + qb));   // (sum, sqsum) reduced together
        float S, Q; up2(t, S, Q);
        float m = S * (1.0f / 128.0f);
        float r = rsqrtf(fmaxf(Q * (1.0f / 128.0f) - m * m, 0.0f) + eps);
        ull nm = dup2(-m), rr = dup2(r);
        o[px][0] = mul2(add2(v[px][0], nm), rr);
        o[px][1] = mul2(add2(v[px][1], nm), rr);
    }
}

__device__ __forceinline__ float gelu_t(float x) {
    float u = 0.7978845608028654f * (x + 0.044715f * x * x * x);
    return 0.5f * x * (1.0f + tanhf(u));
}
__device__ __forceinline__ float gelu_e(float x) { return 0.5f * x * (1.0f + erff(x * 0.7071067811865475f)); }
__device__ __forceinline__ ull gelu_e2(ull v) { float a, b; up2(v, a, b); return pk2(gelu_e(a), gelu_e(b)); }

__device__ __forceinline__ float4 ldg4(const float* p) {
    return __ldg(reinterpret_cast<const float4*>(p));
}
__device__ __forceinline__ ulonglong2 ldg2(const float* p) {
    return __ldg(reinterpret_cast<const ulonglong2*>(p));
}

// MOV-dup GEMV (pixel-paired acts in smem, weights duplicated): used for multi-row k/v/WB, fc2
template <int NIN, int ROWS, int NG, int STRIDE>
__device__ __forceinline__ void mv2(const float* __restrict__ W, const float* __restrict__ act,
                                    int actStride, int o4, ull* acc) {
#pragma unroll 2
    for (int in = 0; in < NIN; ++in) {
        ull wd[NG][4];
#pragma unroll
        for (int r = 0; r < NG; ++r) {
            float4 wv = ldg4(W + in * STRIDE + r * 128 + o4);
            wd[r][0] = dup2(wv.x); wd[r][1] = dup2(wv.y);
            wd[r][2] = dup2(wv.z); wd[r][3] = dup2(wv.w);
        }
#pragma unroll
        for (int row = 0; row < ROWS; ++row) {
            ull a0 = ldp(act + row * actStride, in * 2 + 0);
            ull a1 = ldp(act + row * actStride, in * 2 + 1);
            ull* ar = acc + row * (2 * NG * 4);
#pragma unroll
            for (int r = 0; r < NG; ++r)
#pragma unroll
                for (int i = 0; i < 4; ++i) {
                    ar[r * 4 + i]          = fma2(a0, wd[r][i], ar[r * 4 + i]);
                    ar[NG * 4 + r * 4 + i] = fma2(a1, wd[r][i], ar[NG * 4 + r * 4 + i]);
                }
        }
    }
}

// pair-scheme GEMV: weights as natural channel-pairs (0 MOVs), acts dup'd in smem.
// acc[(px*NG+g)*2+cp] += act[px][in] * W[in][g*128+o4+2cp+{0,1}]
template <int NIN, int NG, int STRIDE>
__device__ __forceinline__ void mvP(const float* __restrict__ W, const float* __restrict__ actd,
                                    int o4, ull* acc) {
#pragma unroll 4
    for (int in = 0; in < NIN; ++in) {
        ulonglong2 wp[NG];
#pragma unroll
        for (int g = 0; g < NG; ++g)
            wp[g] = ldg2(W + in * STRIDE + g * 128 + o4);
#pragma unroll
        for (int px = 0; px < 4; ++px) {
            ull a = ldd(actd, in * 4 + px);
#pragma unroll
            for (int g = 0; g < NG; ++g) {
                acc[(px * NG + g) * 2 + 0] = fma2(a, wp[g].x, acc[(px * NG + g) * 2 + 0]);
                acc[(px * NG + g) * 2 + 1] = fma2(a, wp[g].y, acc[(px * NG + g) * 2 + 1]);
            }
        }
    }
}

// store channel-paired [4][2] vector dup'd into sxd
__device__ __forceinline__ void storeP_dup(float* sxd, int o4, const ull t[4][2]) {
#pragma unroll
    for (int px = 0; px < 4; ++px)
#pragma unroll
        for (int cp = 0; cp < 2; ++cp) {
            float a, b; up2(t[px][cp], a, b);
            sdd(sxd, (o4 + 2 * cp) * 4 + px, a);
            sdd(sxd, (o4 + 2 * cp + 1) * 4 + px, b);
        }
}

__global__ __launch_bounds__(64, 8)
void upsample_tf_kernel(
    const float* __restrict__ feat, const float* __restrict__ featup,
    const float* __restrict__ ctx_ln_b,
    const float* __restrict__ q_w, const float* __restrict__ q_b,
    const float* __restrict__ k_w, const float* __restrict__ k_b,
    const float* __restrict__ v_w, const float* __restrict__ v_b,
    const float* __restrict__ o_w, const float* __restrict__ o_b,
    const float* __restrict__ fc1_w, const float* __restrict__ fc1_b,
    const float* __restrict__ fc2_w, const float* __restrict__ fc2_b,
    const float* __restrict__ out1_b,
    const float* __restrict__ out2_w, const float* __restrict__ out2_b,
    const float* __restrict__ ctx_ln_g,
    float* __restrict__ out)
{
    __shared__ __align__(16) float s_xd[2][1024];     // dup'd: xn/ov/hn/xf
    __shared__ __align__(16) float s_c[2][4][512];    // paired: cn / fc1 hidden / cf
    __shared__ __align__(16) float s_a[2][4][16];     // final logits staging

    const int w = threadIdx.x >> 5, ln = threadIdx.x & 31, o4 = ln * 4;
    const int g = blockIdx.x * 2 + w;
    const int n0 = g * 4;
    if (n0 >= kN) return;
    const int b = n0 / kHWu;
    const int rr = n0 - b * kHWu;
    const int hu = rr / kWu, wu0 = rr - hu * kWu;

    float* sxd = s_xd[w];
    float* sc = &s_c[w][0][0];
    float (*sa)[16] = s_a[w];

    const int rh0 = min(hu >> 1, kHd - 1), rh1 = min((hu >> 1) + 1, kHd - 1);
    const int hd = ln >> 3;
    const float slope = exp2f(-(float)(hd + 1) * 1.1462406251802891f); // log2(24)/4

    // ---- x load, transposed to channel-paired per pixel
    ull x2[4][2];
    {
        const float* fu = featup + ((size_t)b * kC) * kHWu + (size_t)hu * kWu + wu0;
        float4 p0 = ldg4(fu + (size_t)(o4 + 0) * kHWu);
        float4 p1 = ldg4(fu + (size_t)(o4 + 1) * kHWu);
        float4 p2 = ldg4(fu + (size_t)(o4 + 2) * kHWu);
        float4 p3 = ldg4(fu + (size_t)(o4 + 3) * kHWu);
        x2[0][0] = pk2(p0.x, p1.x); x2[0][1] = pk2(p2.x, p3.x);
        x2[1][0] = pk2(p0.y, p1.y); x2[1][1] = pk2(p2.y, p3.y);
        x2[2][0] = pk2(p0.z, p1.z); x2[2][1] = pk2(p2.z, p3.z);
        x2[3][0] = pk2(p0.w, p1.w); x2[3][1] = pk2(p2.w, p3.w);
    }

    auto loadctx = [&](int j, ull cv[2][4]) {
        const int ky = j >> 1, kx = j & 1;
        const int rhv = ky ? rh1 : rh0;
        const float* fm = feat + ((size_t)b * kC) * kHWd + rhv * kWd;
#pragma unroll
        for (int i = 0; i < 4; ++i) {
            const float* cp = fm + (size_t)(o4 + i) * kHWd;
            float v0 = __ldg(cp + min(((wu0 + 0) >> 1) + kx, kWd - 1));
            float v1 = __ldg(cp + min(((wu0 + 1) >> 1) + kx, kWd - 1));
            float v2 = __ldg(cp + min(((wu0 + 2) >> 1) + kx, kWd - 1));
            float v3 = __ldg(cp + min(((wu0 + 3) >> 1) + kx, kWd - 1));
            cv[0][i] = pk2(v0, v1);
            cv[1][i] = pk2(v2, v3);
        }
    };

#pragma unroll 1
    for (int l = 0; l < 2; ++l) {
        const float* qW  = q_w  + l * 16384;
        const float* kW  = k_w  + l * 16384;
        const float* vW  = v_w  + l * 16384;
        const float* oW  = o_w  + l * 16384;
        const float* f1W = fc1_w + l * 65536;
        const float* f2W = fc2_w + l * 65536;

        // xn = LN(x) -> sxd (dup'd)
        ull t[4][2];
        lnP(x2, 1e-6f, t);
        __syncwarp();   // previous readers of sxd done
        storeP_dup(sxd, o4, t);

        // cn = LN(ctx,1e-5)*g + b -> sc (paired)
        {
            float4 gg = ldg4(ctx_ln_g + l * 128 + o4);
            float4 bb = ldg4(ctx_ln_b + l * 128 + o4);
            ull gd[4] = {dup2(gg.x), dup2(gg.y), dup2(gg.z), dup2(gg.w)};
            ull bd[4] = {dup2(bb.x), dup2(bb.y), dup2(bb.z), dup2(bb.w)};
#pragma unroll 1
            for (int j = 0; j < 4; ++j) {
                ull cv[2][4], cn[2][4];
                loadctx(j, cv);
                ln2(cv[0], 1e-5f, cn[0]);
                ln2(cv[1], 1e-5f, cn[1]);
#pragma unroll
                for (int pr = 0; pr < 2; ++pr)
#pragma unroll
                    for (int i = 0; i < 4; ++i)
                        stp(sc + j * 512, (o4 + i) * 2 + pr, fma2(cn[pr][i], gd[i], bd[i]));
            }
        }
        __syncwarp();

        // q = xn @ q_w + q_b   (pair scheme, channel-paired out)
        ull qa8[8];
        {
            ulonglong2 bp = ldg2(q_b + l * 128 + o4);
#pragma unroll
            for (int px = 0; px < 4; ++px) { qa8[px * 2] = bp.x; qa8[px * 2 + 1] = bp.y; }
        }
        mvP<128, 1, 128>(qW, sxd, o4, qa8);
        // repack q to pixel-paired for score dot
        ull qp[2][4];
        {
            float qs[4][4];
#pragma unroll
            for (int px = 0; px < 4; ++px)
#pragma unroll
                for (int cp = 0; cp < 2; ++cp) up2(qa8[px * 2 + cp], qs[px][2 * cp], qs[px][2 * cp + 1]);
#pragma unroll
            for (int pr = 0; pr < 2; ++pr)
#pragma unroll
                for (int i = 0; i < 4; ++i) qp[pr][i] = pk2(qs[2 * pr][i], qs[2 * pr + 1][i]);
        }

        // k: all 4 ctx rows in one pass, folded into scores
        ull sc2[4][2];
        {
            ull ka[32];
            float4 kb = ldg4(k_b + l * 128 + o4);
            ull kb2[4] = {dup2(kb.x), dup2(kb.y), dup2(kb.z), dup2(kb.w)};
#pragma unroll
            for (int j = 0; j < 4; ++j)
#pragma unroll
                for (int pr = 0; pr < 2; ++pr)
#pragma unroll
                    for (int i = 0; i < 4; ++i) ka[j * 8 + pr * 4 + i] = kb2[i];
            mv2<128, 4, 1, 128>(kW, sc, 512, o4, ka);
#pragma unroll
            for (int j = 0; j < 4; ++j)
#pragma unroll
                for (int pr = 0; pr < 2; ++pr) {
                    ull p = mul2(qp[pr][0], ka[j * 8 + pr * 4 + 0]);
                    p = fma2(qp[pr][1], ka[j * 8 + pr * 4 + 1], p);
                    p = fma2(qp[pr][2], ka[j * 8 + pr * 4 + 2], p);
                    p = fma2(qp[pr][3], ka[j * 8 + pr * 4 + 3], p);
                    p = add2(p, __shfl_xor_sync(0xffffffffu, p, 1));
                    p = add2(p, __shfl_xor_sync(0xffffffffu, p, 2));
                    p = add2(p, __shfl_xor_sync(0xffffffffu, p, 4));
                    sc2[j][pr] = p;
                }
        }

        // softmax with ALiBi, per pixel (redundant per lane)
        ull a2[4][2];
        {
#pragma unroll
            for (int pr = 0; pr < 2; ++pr) {
                float sj[2][4];
#pragma unroll
                for (int j = 0; j < 4; ++j) {
                    float pa, pb; up2(sc2[j][pr], pa, pb);
                    const int ky = j >> 1, kx = j & 1;
                    const int rhv = ky ? rh1 : rh0;
#pragma unroll
                    for (int tt = 0; tt < 2; ++tt) {
                        int wup = wu0 + pr * 2 + tt;
                        int rwv = min((wup >> 1) + kx, kWd - 1);
                        float cd = -(float)(abs(hu - 2 * rhv) + abs(wup - 2 * rwv));
                        sj[tt][j] = (tt ? pb : pa) * 0.17677669529663687f + slope * cd;
                    }
                }
                float av[2][4];
#pragma unroll
                for (int tt = 0; tt < 2; ++tt) {
                    float mx = fmaxf(fmaxf(sj[tt][0], sj[tt][1]), fmaxf(sj[tt][2], sj[tt][3]));
                    float e0 = expf(sj[tt][0] - mx), e1 = expf(sj[tt][1] - mx);
                    float e2 = expf(sj[tt][2] - mx), e3 = expf(sj[tt][3] - mx);
                    float inv = 1.0f / (e0 + e1 + e2 + e3);
                    av[tt][0] = e0 * inv; av[tt][1] = e1 * inv;
                    av[tt][2] = e2 * inv; av[tt][3] = e3 * inv;
                }
#pragma unroll
                for (int j = 0; j < 4; ++j) a2[j][pr] = pk2(av[0][j], av[1][j]);
            }
        }

        // v in 2-row passes folded into ov (pixel-paired)
        ull ov[2][4];
        {
            float4 vb = ldg4(v_b + l * 128 + o4);
            ull vb2[4] = {dup2(vb.x), dup2(vb.y), dup2(vb.z), dup2(vb.w)};
#pragma unroll
            for (int pr = 0; pr < 2; ++pr)
#pragma unroll
                for (int i = 0; i < 4; ++i) ov[pr][i] = pk2(0.f, 0.f);
#pragma unroll 1
            for (int jp = 0; jp < 2; ++jp) {
                ull va[16];
#pragma unroll
                for (int row = 0; row < 2; ++row)
#pragma unroll
                    for (int pr = 0; pr < 2; ++pr)
#pragma unroll
                        for (int i = 0; i < 4; ++i) va[row * 8 + pr * 4 + i] = vb2[i];
                mv2<128, 2, 1, 128>(vW, sc + jp * 1024, 512, o4, va);
#pragma unroll
                for (int row = 0; row < 2; ++row)
#pragma unroll
                    for (int pr = 0; pr < 2; ++pr)
#pragma unroll
                        for (int i = 0; i < 4; ++i)
                            ov[pr][i] = fma2(a2[jp * 2 + row][pr], va[row * 8 + pr * 4 + i], ov[pr][i]);
            }
        }
        __syncwarp();   // q-pass reads of sxd done
        // store ov dup'd
#pragma unroll
        for (int pr = 0; pr < 2; ++pr)
#pragma unroll
            for (int i = 0; i < 4; ++i) {
                float a, bv; up2(ov[pr][i], a, bv);
                sdd(sxd, (o4 + i) * 4 + 2 * pr + 0, a);
                sdd(sxd, (o4 + i) * 4 + 2 * pr + 1, bv);
            }
        __syncwarp();

        // x += o @ o_w + o_b  (pair scheme, adds directly to channel-paired x2)
        {
            ull oa8[8];
            ulonglong2 bp = ldg2(o_b + l * 128 + o4);
#pragma unroll
            for (int px = 0; px < 4; ++px) { oa8[px * 2] = bp.x; oa8[px * 2 + 1] = bp.y; }
            mvP<128, 1, 128>(oW, sxd, o4, oa8);
#pragma unroll
            for (int px = 0; px < 4; ++px) {
                x2[px][0] = add2(x2[px][0], oa8[px * 2 + 0]);
                x2[px][1] = add2(x2[px][1], oa8[px * 2 + 1]);
            }
        }

        // MLP
        lnP(x2, 1e-6f, t);
        __syncwarp();   // o-proj reads of sxd done
        storeP_dup(sxd, o4, t);
        __syncwarp();

        // fc1: NG=4 pair scheme
        {
            ull f1[32];   // [(px*4+g)*2+cp]
#pragma unroll
            for (int gg = 0; gg < 4; ++gg) {
                ulonglong2 bp = ldg2(fc1_b + l * 512 + gg * 128 + o4);
#pragma unroll
                for (int px = 0; px < 4; ++px) {
                    f1[(px * 4 + gg) * 2 + 0] = bp.x;
                    f1[(px * 4 + gg) * 2 + 1] = bp.y;
                }
            }
            mvP<128, 4, 512>(f1W, sxd, o4, f1);
            __syncwarp();   // v-pass reads of sc done
#pragma unroll
            for (int gg = 0; gg < 4; ++gg)
#pragma unroll
                for (int cp = 0; cp < 2; ++cp) {
                    float a0, b0, a1, b1, a2_, b2, a3, b3;
                    up2(f1[(0 * 4 + gg) * 2 + cp], a0, b0);
                    up2(f1[(1 * 4 + gg) * 2 + cp], a1, b1);
                    up2(f1[(2 * 4 + gg) * 2 + cp], a2_, b2);
                    up2(f1[(3 * 4 + gg) * 2 + cp], a3, b3);
                    int c0 = gg * 128 + o4 + 2 * cp, c1 = c0 + 1;
                    stp(sc, c0 * 2 + 0, pk2(gelu_t(a0), gelu_t(a1)));
                    stp(sc, c0 * 2 + 1, pk2(gelu_t(a2_), gelu_t(a3)));
                    stp(sc, c1 * 2 + 0, pk2(gelu_t(b0), gelu_t(b1)));
                    stp(sc, c1 * 2 + 1, pk2(gelu_t(b2), gelu_t(b3)));
                }
            __syncwarp();
        }

        // fc2 on paired hidden
        {
            ull fa8[8];
            float4 fb = ldg4(fc2_b + l * 128 + o4);
            fa8[0] = fa8[4] = dup2(fb.x); fa8[1] = fa8[5] = dup2(fb.y);
            fa8[2] = fa8[6] = dup2(fb.z); fa8[3] = fa8[7] = dup2(fb.w);
            mv2<512, 1, 1, 128>(f2W, sc, 0, o4, fa8);
            // transpose pixel-paired -> channel-paired and add
            float tpx[4][4];
#pragma unroll
            for (int pr = 0; pr < 2; ++pr)
#pragma unroll
                for (int i = 0; i < 4; ++i) up2(fa8[pr * 4 + i], tpx[2 * pr][i], tpx[2 * pr + 1][i]);
#pragma unroll
            for (int px = 0; px < 4; ++px) {
                x2[px][0] = add2(x2[px][0], pk2(tpx[px][0], tpx[px][1]));
                x2[px][1] = add2(x2[px][1], pk2(tpx[px][2], tpx[px][3]));
            }
        }
        __syncwarp();   // fc2 reads of sc done before next-layer cn overwrite
    }

    // ---- final head
    {
        ull t[4][2];
        lnP(x2, 1e-6f, t);   // xf
        __syncwarp();
        storeP_dup(sxd, o4, t);
#pragma unroll 1
        for (int j = 0; j < 4; ++j) {
            ull cv[2][4], cf[2][4];
            loadctx(j, cv);
            ln2(cv[0], 1e-6f, cf[0]);
            ln2(cv[1], 1e-6f, cf[1]);
#pragma unroll
            for (int pr = 0; pr < 2; ++pr)
#pragma unroll
                for (int i = 0; i < 4; ++i) stp(sc + j * 512, (o4 + i) * 2 + pr, cf[pr][i]);
        }
        __syncwarp();

        ull s2[4][2];
#pragma unroll
        for (int j = 0; j < 4; ++j) { s2[j][0] = pk2(0.f, 0.f); s2[j][1] = pk2(0.f, 0.f); }

#pragma unroll 1
        for (int r = 0; r < 3; ++r) {
            // tb = out1_b[r] + xf @ WA[:,r-cols]  (pair scheme)
            ull tb8[8];
            {
                ulonglong2 bp = ldg2(out1_b + r * 128 + o4);
#pragma unroll
                for (int px = 0; px < 4; ++px) { tb8[px * 2] = bp.x; tb8[px * 2 + 1] = bp.y; }
            }
            mvP<128, 1, 384>(g_WA + r * 128, sxd, o4, tb8);
            // transpose to pixel-paired
            ull tpp[2][4];
            {
                float ts[4][4];
#pragma unroll
                for (int px = 0; px < 4; ++px)
#pragma unroll
                    for (int cp = 0; cp < 2; ++cp) up2(tb8[px * 2 + cp], ts[px][2 * cp], ts[px][2 * cp + 1]);
#pragma unroll
                for (int pr = 0; pr < 2; ++pr)
#pragma unroll
                    for (int i = 0; i < 4; ++i) tpp[pr][i] = pk2(ts[2 * pr][i], ts[2 * pr + 1][i]);
            }

            float4 w2v = ldg4(out2_w + r * 128 + o4);
            ull wd[4] = {dup2(w2v.x), dup2(w2v.y), dup2(w2v.z), dup2(w2v.w)};

#pragma unroll 1
            for (int jp = 0; jp < 2; ++jp) {
                ull us[16];
#pragma unroll
                for (int tt = 0; tt < 16; ++tt) us[tt] = pk2(0.f, 0.f);
                mv2<128, 2, 1, 384>(g_WB + r * 128, sc + jp * 1024, 512, o4, us);
#pragma unroll
                for (int row = 0; row < 2; ++row)
#pragma unroll
                    for (int pr = 0; pr < 2; ++pr)
#pragma unroll
                        for (int i = 0; i < 4; ++i)
                            s2[jp * 2 + row][pr] = fma2(gelu_e2(add2(tpp[pr][i], us[row * 8 + pr * 4 + i])),
                                                        wd[i], s2[jp * 2 + row][pr]);
            }
        }

        const float o2b = __ldg(out2_b);
#pragma unroll
        for (int j = 0; j < 4; ++j)
#pragma unroll
            for (int pr = 0; pr < 2; ++pr) {
                ull tt = wsum2(s2[j][pr]);
                float a, bv; up2(tt, a, bv);
                if (ln == 0) {
                    sa[pr * 2][j] = a + o2b;
                    sa[pr * 2 + 1][j] = bv + o2b;
                }
            }
        __syncwarp();

        if (ln < 16) {
            int p = ln >> 2, j = ln & 3;
            float l0 = sa[p][0], l1 = sa[p][1], l2 = sa[p][2], l3 = sa[p][3];
            float mx = fmaxf(fmaxf(l0, l1), fmaxf(l2, l3));
            float den = expf(l0 - mx) + expf(l1 - mx) + expf(l2 - mx) + expf(l3 - mx);
            float e = expf(sa[p][j] - mx);
            out[(((size_t)b * 4 + j) * kHu + hu) * kWu + wu0 + p] = e / den;
        }
    }
}

extern "C" void kernel_launch(void* const* d_in, const int* in_sizes, int n_in,
                              void* d_out, int out_size) {
    const float* feat     = (const float*)d_in[0];
    const float* featup   = (const float*)d_in[1];
    const float* ctx_ln_b = (const float*)d_in[2];
    const float* q_w      = (const float*)d_in[3];
    const float* q_b      = (const float*)d_in[4];
    const float* k_w      = (const float*)d_in[5];
    const float* k_b      = (const float*)d_in[6];
    const float* v_w      = (const float*)d_in[7];
    const float* v_b      = (const float*)d_in[8];
    const float* o_w      = (const float*)d_in[9];
    const float* o_b      = (const float*)d_in[10];
    const float* fc1_w    = (const float*)d_in[11];
    const float* fc1_b    = (const float*)d_in[12];
    const float* fc2_w    = (const float*)d_in[13];
    const float* fc2_b    = (const float*)d_in[14];
    const float* out1_w   = (const float*)d_in[15];
    const float* out1_b   = (const float*)d_in[16];
    const float* out2_w   = (const float*)d_in[17];
    const float* out2_b   = (const float*)d_in[18];
    const float* ctx_ln_g = (const float*)d_in[19];

    prep_kernel<<<(128 * 384 + 255) / 256, 256>>>(out1_w);
    upsample_tf_kernel<<<kN / 8, 64>>>(
        feat, featup, ctx_ln_b, q_w, q_b, k_w, k_b, v_w, v_b, o_w, o_b,
        fc1_w, fc1_b, fc2_w, fc2_b, out1_b, out2_w, out2_b, ctx_ln_g,
        (float*)d_out);
}

// round 8
// speedup vs baseline: 1.9717x; 1.0015x over previous
#include <cuda_runtime.h>
#include <math.h>

typedef unsigned long long ull;

namespace {
constexpr int kB = 2, kC = 128, kHd = 64, kWd = 96, kHu = 128, kWu = 192;
constexpr int kN = kB * kHu * kWu;
constexpr int kHWd = kHd * kWd, kHWu = kHu * kWu;
}

// Precombined final-head weights: fin=[xf,cf,xf-cf] => fin@W = xf@(W0+W2) + cf@(W1-W2)
__device__ float g_WA[128 * 384];
__device__ float g_WB[128 * 384];

__global__ void prep_kernel(const float* __restrict__ o1w) {
    int i = blockIdx.x * blockDim.x + threadIdx.x;
    if (i < 128 * 384) {
        int in = i / 384, o = i - in * 384;
        float w2 = o1w[(256 + in) * 384 + o];
        g_WA[i] = o1w[in * 384 + o] + w2;
        g_WB[i] = o1w[(128 + in) * 384 + o] - w2;
    }
}

// ---- packed f32x2 helpers (SASS FFMA2 path, PTX-only) ----
__device__ __forceinline__ ull pk2(float a, float b) {
    ull r; asm("mov.b64 %0,{%1,%2};" : "=l"(r) : "f"(a), "f"(b)); return r;
}
__device__ __forceinline__ ull dup2(float a) { return pk2(a, a); }
__device__ __forceinline__ void up2(ull v, float& a, float& b) {
    asm("mov.b64 {%0,%1},%2;" : "=f"(a), "=f"(b) : "l"(v));
}
__device__ __forceinline__ ull fma2(ull a, ull b, ull c) {
    ull d; asm("fma.rn.f32x2 %0,%1,%2,%3;" : "=l"(d) : "l"(a), "l"(b), "l"(c)); return d;
}
__device__ __forceinline__ ull add2(ull a, ull b) {
    ull d; asm("add.rn.f32x2 %0,%1,%2;" : "=l"(d) : "l"(a), "l"(b)); return d;
}
__device__ __forceinline__ ull mul2(ull a, ull b) {
    ull d; asm("mul.rn.f32x2 %0,%1,%2;" : "=l"(d) : "l"(a), "l"(b)); return d;
}

// paired smem (4B per (ch,pixel), pixel-pair packed) with XOR swizzle
__device__ __forceinline__ int swzi(int f2) { return f2 ^ ((f2 >> 4) & 15); }
__device__ __forceinline__ ull ldp(const float* b, int f2) {
    return *reinterpret_cast<const ull*>(b + 2 * swzi(f2));
}
__device__ __forceinline__ void stp(float* b, int f2, ull v) {
    *reinterpret_cast<ull*>(b + 2 * swzi(f2)) = v;
}

// dup'd smem (8B per (ch,pixel), scalar stored twice). slot s = ch*4+px.
__device__ __forceinline__ ull ldd(const float* b, int s) {
    int sw = s ^ ((s >> 4) & 15);
    return *reinterpret_cast<const ull*>(b + 2 * sw);
}
__device__ __forceinline__ void sdd(float* b, int s, float v) {
    int sw = s ^ ((s >> 4) & 15);
    b[2 * sw] = v; b[2 * sw + 1] = v;
}

__device__ __forceinline__ ull wsum2(ull v) {
#pragma unroll
    for (int o = 16; o; o >>= 1) v = add2(v, __shfl_xor_sync(0xffffffffu, v, o));
    return v;
}

// pixel-paired LayerNorm (for ctx rows): v[i] packs channel (o4+i) of two pixels
__device__ __forceinline__ void ln2(const ull v[4], float eps, ull o[4]) {
    ull s = add2(add2(v[0], v[1]), add2(v[2], v[3]));
    ull q = fma2(v[0], v[0], fma2(v[1], v[1], fma2(v[2], v[2], mul2(v[3], v[3]))));
    s = wsum2(s); q = wsum2(q);
    float s0, s1, q0, q1; up2(s, s0, s1); up2(q, q0, q1);
    float m0 = s0 * (1.0f / 128.0f), m1 = s1 * (1.0f / 128.0f);
    float r0 = rsqrtf(fmaxf(q0 * (1.0f / 128.0f) - m0 * m0, 0.0f) + eps);
    float r1 = rsqrtf(fmaxf(q1 * (1.0f / 128.0f) - m1 * m1, 0.0f) + eps);
    ull nm = pk2(-m0, -m1), rr = pk2(r0, r1);
#pragma unroll
    for (int i = 0; i < 4; ++i) o[i] = mul2(add2(v[i], nm), rr);
}

// channel-paired per-pixel LayerNorm: v[px][cp] packs channels (o4+2cp, o4+2cp+1)
__device__ __forceinline__ void lnP(const ull v[4][2], float eps, ull o[4][2]) {
#pragma unroll
    for (int px = 0; px < 4; ++px) {
        ull s2 = add2(v[px][0], v[px][1]);
        ull q2 = fma2(v[px][0], v[px][0], mul2(v[px][1], v[px][1]));
        float sa, sb, qa, qb; up2(s2, sa, sb); up2(q2, qa, qb);
        ull t = wsum2(pk2(sa + sb, qa + qb));   // (sum, sqsum) reduced together
        float S, Q; up2(t, S, Q);
        float m = S * (1.0f / 128.0f);
        float r = rsqrtf(fmaxf(Q * (1.0f / 128.0f) - m * m, 0.0f) + eps);
        ull nm = dup2(-m), rr = dup2(r);
        o[px][0] = mul2(add2(v[px][0], nm), rr);
        o[px][1] = mul2(add2(v[px][1], nm), rr);
    }
}

__device__ __forceinline__ float gelu_t(float x) {
    float u = 0.7978845608028654f * (x + 0.044715f * x * x * x);
    return 0.5f * x * (1.0f + tanhf(u));
}
__device__ __forceinline__ float gelu_e(float x) { return 0.5f * x * (1.0f + erff(x * 0.7071067811865475f)); }
__device__ __forceinline__ ull gelu_e2(ull v) { float a, b; up2(v, a, b); return pk2(gelu_e(a), gelu_e(b)); }

__device__ __forceinline__ float4 ldg4(const float* p) {
    return __ldg(reinterpret_cast<const float4*>(p));
}
__device__ __forceinline__ ulonglong2 ldg2(const float* p) {
    return __ldg(reinterpret_cast<const ulonglong2*>(p));
}

// MOV-dup GEMV (pixel-paired acts in smem, weights duplicated): used for multi-row k/v/WB, fc2
template <int NIN, int ROWS, int NG, int STRIDE>
__device__ __forceinline__ void mv2(const float* __restrict__ W, const float* __restrict__ act,
                                    int actStride, int o4, ull* acc) {
#pragma unroll 2
    for (int in = 0; in < NIN; ++in) {
        ull wd[NG][4];
#pragma unroll
        for (int r = 0; r < NG; ++r) {
            float4 wv = ldg4(W + in * STRIDE + r * 128 + o4);
            wd[r][0] = dup2(wv.x); wd[r][1] = dup2(wv.y);
            wd[r][2] = dup2(wv.z); wd[r][3] = dup2(wv.w);
        }
#pragma unroll
        for (int row = 0; row < ROWS; ++row) {
            ull a0 = ldp(act + row * actStride, in * 2 + 0);
            ull a1 = ldp(act + row * actStride, in * 2 + 1);
            ull* ar = acc + row * (2 * NG * 4);
#pragma unroll
            for (int r = 0; r < NG; ++r)
#pragma unroll
                for (int i = 0; i < 4; ++i) {
                    ar[r * 4 + i]          = fma2(a0, wd[r][i], ar[r * 4 + i]);
                    ar[NG * 4 + r * 4 + i] = fma2(a1, wd[r][i], ar[NG * 4 + r * 4 + i]);
                }
        }
    }
}

// pair-scheme GEMV: weights as natural channel-pairs (0 MOVs), acts dup'd in smem.
// acc[(px*NG+g)*2+cp] += act[px][in] * W[in][g*128+o4+2cp+{0,1}]
template <int NIN, int NG, int STRIDE>
__device__ __forceinline__ void mvP(const float* __restrict__ W, const float* __restrict__ actd,
                                    int o4, ull* acc) {
#pragma unroll 4
    for (int in = 0; in < NIN; ++in) {
        ulonglong2 wp[NG];
#pragma unroll
        for (int g = 0; g < NG; ++g)
            wp[g] = ldg2(W + in * STRIDE + g * 128 + o4);
#pragma unroll
        for (int px = 0; px < 4; ++px) {
            ull a = ldd(actd, in * 4 + px);
#pragma unroll
            for (int g = 0; g < NG; ++g) {
                acc[(px * NG + g) * 2 + 0] = fma2(a, wp[g].x, acc[(px * NG + g) * 2 + 0]);
                acc[(px * NG + g) * 2 + 1] = fma2(a, wp[g].y, acc[(px * NG + g) * 2 + 1]);
            }
        }
    }
}

// store channel-paired [4][2] vector dup'd into sxd
__device__ __forceinline__ void storeP_dup(float* sxd, int o4, const ull t[4][2]) {
#pragma unroll
    for (int px = 0; px < 4; ++px)
#pragma unroll
        for (int cp = 0; cp < 2; ++cp) {
            float a, b; up2(t[px][cp], a, b);
            sdd(sxd, (o4 + 2 * cp) * 4 + px, a);
            sdd(sxd, (o4 + 2 * cp + 1) * 4 + px, b);
        }
}

__global__ __launch_bounds__(64, 8)
void upsample_tf_kernel(
    const float* __restrict__ feat, const float* __restrict__ featup,
    const float* __restrict__ ctx_ln_b,
    const float* __restrict__ q_w, const float* __restrict__ q_b,
    const float* __restrict__ k_w, const float* __restrict__ k_b,
    const float* __restrict__ v_w, const float* __restrict__ v_b,
    const float* __restrict__ o_w, const float* __restrict__ o_b,
    const float* __restrict__ fc1_w, const float* __restrict__ fc1_b,
    const float* __restrict__ fc2_w, const float* __restrict__ fc2_b,
    const float* __restrict__ out1_b,
    const float* __restrict__ out2_w, const float* __restrict__ out2_b,
    const float* __restrict__ ctx_ln_g,
    float* __restrict__ out)
{
    __shared__ __align__(16) float s_xd[2][1024];     // dup'd: xn/ov/hn/xf
    __shared__ __align__(16) float s_c[2][4][512];    // paired: cn / fc1 hidden / cf
    __shared__ __align__(16) float s_a[2][4][16];     // final logits staging

    const int w = threadIdx.x >> 5, ln = threadIdx.x & 31, o4 = ln * 4;
    const int g = blockIdx.x * 2 + w;
    const int n0 = g * 4;
    if (n0 >= kN) return;
    const int b = n0 / kHWu;
    const int rr = n0 - b * kHWu;
    const int hu = rr / kWu, wu0 = rr - hu * kWu;

    float* sxd = s_xd[w];
    float* sc = &s_c[w][0][0];
    float (*sa)[16] = s_a[w];

    const int rh0 = min(hu >> 1, kHd - 1), rh1 = min((hu >> 1) + 1, kHd - 1);
    const int hd = ln >> 3;
    const float slope = exp2f(-(float)(hd + 1) * 1.1462406251802891f); // log2(24)/4

    // ---- x load, transposed to channel-paired per pixel
    ull x2[4][2];
    {
        const float* fu = featup + ((size_t)b * kC) * kHWu + (size_t)hu * kWu + wu0;
        float4 p0 = ldg4(fu + (size_t)(o4 + 0) * kHWu);
        float4 p1 = ldg4(fu + (size_t)(o4 + 1) * kHWu);
        float4 p2 = ldg4(fu + (size_t)(o4 + 2) * kHWu);
        float4 p3 = ldg4(fu + (size_t)(o4 + 3) * kHWu);
        x2[0][0] = pk2(p0.x, p1.x); x2[0][1] = pk2(p2.x, p3.x);
        x2[1][0] = pk2(p0.y, p1.y); x2[1][1] = pk2(p2.y, p3.y);
        x2[2][0] = pk2(p0.z, p1.z); x2[2][1] = pk2(p2.z, p3.z);
        x2[3][0] = pk2(p0.w, p1.w); x2[3][1] = pk2(p2.w, p3.w);
    }

    auto loadctx = [&](int j, ull cv[2][4]) {
        const int ky = j >> 1, kx = j & 1;
        const int rhv = ky ? rh1 : rh0;
        const float* fm = feat + ((size_t)b * kC) * kHWd + rhv * kWd;
#pragma unroll
        for (int i = 0; i < 4; ++i) {
            const float* cp = fm + (size_t)(o4 + i) * kHWd;
            float v0 = __ldg(cp + min(((wu0 + 0) >> 1) + kx, kWd - 1));
            float v1 = __ldg(cp + min(((wu0 + 1) >> 1) + kx, kWd - 1));
            float v2 = __ldg(cp + min(((wu0 + 2) >> 1) + kx, kWd - 1));
            float v3 = __ldg(cp + min(((wu0 + 3) >> 1) + kx, kWd - 1));
            cv[0][i] = pk2(v0, v1);
            cv[1][i] = pk2(v2, v3);
        }
    };

#pragma unroll 1
    for (int l = 0; l < 2; ++l) {
        const float* qW  = q_w  + l * 16384;
        const float* kW  = k_w  + l * 16384;
        const float* vW  = v_w  + l * 16384;
        const float* oW  = o_w  + l * 16384;
        const float* f1W = fc1_w + l * 65536;
        const float* f2W = fc2_w + l * 65536;

        // xn = LN(x) -> sxd (dup'd)
        ull t[4][2];
        lnP(x2, 1e-6f, t);
        __syncwarp();   // previous readers of sxd done
        storeP_dup(sxd, o4, t);

        // cn = LN(ctx,1e-5)*g + b -> sc (paired)
        {
            float4 gg = ldg4(ctx_ln_g + l * 128 + o4);
            float4 bb = ldg4(ctx_ln_b + l * 128 + o4);
            ull gd[4] = {dup2(gg.x), dup2(gg.y), dup2(gg.z), dup2(gg.w)};
            ull bd[4] = {dup2(bb.x), dup2(bb.y), dup2(bb.z), dup2(bb.w)};
#pragma unroll 1
            for (int j = 0; j < 4; ++j) {
                ull cv[2][4], cn[2][4];
                loadctx(j, cv);
                ln2(cv[0], 1e-5f, cn[0]);
                ln2(cv[1], 1e-5f, cn[1]);
#pragma unroll
                for (int pr = 0; pr < 2; ++pr)
#pragma unroll
                    for (int i = 0; i < 4; ++i)
                        stp(sc + j * 512, (o4 + i) * 2 + pr, fma2(cn[pr][i], gd[i], bd[i]));
            }
        }
        __syncwarp();

        // q = xn @ q_w + q_b   (pair scheme, channel-paired out)
        ull qa8[8];
        {
            ulonglong2 bp = ldg2(q_b + l * 128 + o4);
#pragma unroll
            for (int px = 0; px < 4; ++px) { qa8[px * 2] = bp.x; qa8[px * 2 + 1] = bp.y; }
        }
        mvP<128, 1, 128>(qW, sxd, o4, qa8);
        // repack q to pixel-paired for score dot
        ull qp[2][4];
        {
            float qs[4][4];
#pragma unroll
            for (int px = 0; px < 4; ++px)
#pragma unroll
                for (int cp = 0; cp < 2; ++cp) up2(qa8[px * 2 + cp], qs[px][2 * cp], qs[px][2 * cp + 1]);
#pragma unroll
            for (int pr = 0; pr < 2; ++pr)
#pragma unroll
                for (int i = 0; i < 4; ++i) qp[pr][i] = pk2(qs[2 * pr][i], qs[2 * pr + 1][i]);
        }

        // k: all 4 ctx rows in one pass, folded into scores
        ull sc2[4][2];
        {
            ull ka[32];
            float4 kb = ldg4(k_b + l * 128 + o4);
            ull kb2[4] = {dup2(kb.x), dup2(kb.y), dup2(kb.z), dup2(kb.w)};
#pragma unroll
            for (int j = 0; j < 4; ++j)
#pragma unroll
                for (int pr = 0; pr < 2; ++pr)
#pragma unroll
                    for (int i = 0; i < 4; ++i) ka[j * 8 + pr * 4 + i] = kb2[i];
            mv2<128, 4, 1, 128>(kW, sc, 512, o4, ka);
#pragma unroll
            for (int j = 0; j < 4; ++j)
#pragma unroll
                for (int pr = 0; pr < 2; ++pr) {
                    ull p = mul2(qp[pr][0], ka[j * 8 + pr * 4 + 0]);
                    p = fma2(qp[pr][1], ka[j * 8 + pr * 4 + 1], p);
                    p = fma2(qp[pr][2], ka[j * 8 + pr * 4 + 2], p);
                    p = fma2(qp[pr][3], ka[j * 8 + pr * 4 + 3], p);
                    p = add2(p, __shfl_xor_sync(0xffffffffu, p, 1));
                    p = add2(p, __shfl_xor_sync(0xffffffffu, p, 2));
                    p = add2(p, __shfl_xor_sync(0xffffffffu, p, 4));
                    sc2[j][pr] = p;
                }
        }

        // softmax with ALiBi, per pixel (redundant per lane)
        ull a2[4][2];
        {
#pragma unroll
            for (int pr = 0; pr < 2; ++pr) {
                float sj[2][4];
#pragma unroll
                for (int j = 0; j < 4; ++j) {
                    float pa, pb; up2(sc2[j][pr], pa, pb);
                    const int ky = j >> 1, kx = j & 1;
                    const int rhv = ky ? rh1 : rh0;
#pragma unroll
                    for (int tt = 0; tt < 2; ++tt) {
                        int wup = wu0 + pr * 2 + tt;
                        int rwv = min((wup >> 1) + kx, kWd - 1);
                        float cd = -(float)(abs(hu - 2 * rhv) + abs(wup - 2 * rwv));
                        sj[tt][j] = (tt ? pb : pa) * 0.17677669529663687f + slope * cd;
                    }
                }
                float av[2][4];
#pragma unroll
                for (int tt = 0; tt < 2; ++tt) {
                    float mx = fmaxf(fmaxf(sj[tt][0], sj[tt][1]), fmaxf(sj[tt][2], sj[tt][3]));
                    float e0 = expf(sj[tt][0] - mx), e1 = expf(sj[tt][1] - mx);
                    float e2 = expf(sj[tt][2] - mx), e3 = expf(sj[tt][3] - mx);
                    float inv = 1.0f / (e0 + e1 + e2 + e3);
                    av[tt][0] = e0 * inv; av[tt][1] = e1 * inv;
                    av[tt][2] = e2 * inv; av[tt][3] = e3 * inv;
                }
#pragma unroll
                for (int j = 0; j < 4; ++j) a2[j][pr] = pk2(av[0][j], av[1][j]);
            }
        }

        // v in 2-row passes folded into ov (pixel-paired)
        ull ov[2][4];
        {
            float4 vb = ldg4(v_b + l * 128 + o4);
            ull vb2[4] = {dup2(vb.x), dup2(vb.y), dup2(vb.z), dup2(vb.w)};
#pragma unroll
            for (int pr = 0; pr < 2; ++pr)
#pragma unroll
                for (int i = 0; i < 4; ++i) ov[pr][i] = pk2(0.f, 0.f);
#pragma unroll 1
            for (int jp = 0; jp < 2; ++jp) {
                ull va[16];
#pragma unroll
                for (int row = 0; row < 2; ++row)
#pragma unroll
                    for (int pr = 0; pr < 2; ++pr)
#pragma unroll
                        for (int i = 0; i < 4; ++i) va[row * 8 + pr * 4 + i] = vb2[i];
                mv2<128, 2, 1, 128>(vW, sc + jp * 1024, 512, o4, va);
#pragma unroll
                for (int row = 0; row < 2; ++row)
#pragma unroll
                    for (int pr = 0; pr < 2; ++pr)
#pragma unroll
                        for (int i = 0; i < 4; ++i)
                            ov[pr][i] = fma2(a2[jp * 2 + row][pr], va[row * 8 + pr * 4 + i], ov[pr][i]);
            }
        }
        __syncwarp();   // q-pass reads of sxd done
        // store ov dup'd
#pragma unroll
        for (int pr = 0; pr < 2; ++pr)
#pragma unroll
            for (int i = 0; i < 4; ++i) {
                float a, bv; up2(ov[pr][i], a, bv);
                sdd(sxd, (o4 + i) * 4 + 2 * pr + 0, a);
                sdd(sxd, (o4 + i) * 4 + 2 * pr + 1, bv);
            }
        __syncwarp();

        // x += o @ o_w + o_b  (pair scheme, adds directly to channel-paired x2)
        {
            ull oa8[8];
            ulonglong2 bp = ldg2(o_b + l * 128 + o4);
#pragma unroll
            for (int px = 0; px < 4; ++px) { oa8[px * 2] = bp.x; oa8[px * 2 + 1] = bp.y; }
            mvP<128, 1, 128>(oW, sxd, o4, oa8);
#pragma unroll
            for (int px = 0; px < 4; ++px) {
                x2[px][0] = add2(x2[px][0], oa8[px * 2 + 0]);
                x2[px][1] = add2(x2[px][1], oa8[px * 2 + 1]);
            }
        }

        // MLP
        lnP(x2, 1e-6f, t);
        __syncwarp();   // o-proj reads of sxd done
        storeP_dup(sxd, o4, t);
        __syncwarp();

        // fc1: NG=4 pair scheme
        {
            ull f1[32];   // [(px*4+g)*2+cp]
#pragma unroll
            for (int gg = 0; gg < 4; ++gg) {
                ulonglong2 bp = ldg2(fc1_b + l * 512 + gg * 128 + o4);
#pragma unroll
                for (int px = 0; px < 4; ++px) {
                    f1[(px * 4 + gg) * 2 + 0] = bp.x;
                    f1[(px * 4 + gg) * 2 + 1] = bp.y;
                }
            }
            mvP<128, 4, 512>(f1W, sxd, o4, f1);
            __syncwarp();   // v-pass reads of sc done
#pragma unroll
            for (int gg = 0; gg < 4; ++gg)
#pragma unroll
                for (int cp = 0; cp < 2; ++cp) {
                    float a0, b0, a1, b1, a2_, b2, a3, b3;
                    up2(f1[(0 * 4 + gg) * 2 + cp], a0, b0);
                    up2(f1[(1 * 4 + gg) * 2 + cp], a1, b1);
                    up2(f1[(2 * 4 + gg) * 2 + cp], a2_, b2);
                    up2(f1[(3 * 4 + gg) * 2 + cp], a3, b3);
                    int c0 = gg * 128 + o4 + 2 * cp, c1 = c0 + 1;
                    stp(sc, c0 * 2 + 0, pk2(gelu_t(a0), gelu_t(a1)));
                    stp(sc, c0 * 2 + 1, pk2(gelu_t(a2_), gelu_t(a3)));
                    stp(sc, c1 * 2 + 0, pk2(gelu_t(b0), gelu_t(b1)));
                    stp(sc, c1 * 2 + 1, pk2(gelu_t(b2), gelu_t(b3)));
                }
            __syncwarp();
        }

        // fc2 on paired hidden
        {
            ull fa8[8];
            float4 fb = ldg4(fc2_b + l * 128 + o4);
            fa8[0] = fa8[4] = dup2(fb.x); fa8[1] = fa8[5] = dup2(fb.y);
            fa8[2] = fa8[6] = dup2(fb.z); fa8[3] = fa8[7] = dup2(fb.w);
            mv2<512, 1, 1, 128>(f2W, sc, 0, o4, fa8);
            // transpose pixel-paired -> channel-paired and add
            float tpx[4][4];
#pragma unroll
            for (int pr = 0; pr < 2; ++pr)
#pragma unroll
                for (int i = 0; i < 4; ++i) up2(fa8[pr * 4 + i], tpx[2 * pr][i], tpx[2 * pr + 1][i]);
#pragma unroll
            for (int px = 0; px < 4; ++px) {
                x2[px][0] = add2(x2[px][0], pk2(tpx[px][0], tpx[px][1]));
                x2[px][1] = add2(x2[px][1], pk2(tpx[px][2], tpx[px][3]));
            }
        }
        __syncwarp();   // fc2 reads of sc done before next-layer cn overwrite
    }

    // ---- final head
    {
        ull t[4][2];
        lnP(x2, 1e-6f, t);   // xf
        __syncwarp();
        storeP_dup(sxd, o4, t);
#pragma unroll 1
        for (int j = 0; j < 4; ++j) {
            ull cv[2][4], cf[2][4];
            loadctx(j, cv);
            ln2(cv[0], 1e-6f, cf[0]);
            ln2(cv[1], 1e-6f, cf[1]);
#pragma unroll
            for (int pr = 0; pr < 2; ++pr)
#pragma unroll
                for (int i = 0; i < 4; ++i) stp(sc + j * 512, (o4 + i) * 2 + pr, cf[pr][i]);
        }
        __syncwarp();

        ull s2[4][2];
#pragma unroll
        for (int j = 0; j < 4; ++j) { s2[j][0] = pk2(0.f, 0.f); s2[j][1] = pk2(0.f, 0.f); }

#pragma unroll 1
        for (int r = 0; r < 3; ++r) {
            // tb = out1_b[r] + xf @ WA[:,r-cols]  (pair scheme)
            ull tb8[8];
            {
                ulonglong2 bp = ldg2(out1_b + r * 128 + o4);
#pragma unroll
                for (int px = 0; px < 4; ++px) { tb8[px * 2] = bp.x; tb8[px * 2 + 1] = bp.y; }
            }
            mvP<128, 1, 384>(g_WA + r * 128, sxd, o4, tb8);
            // transpose to pixel-paired
            ull tpp[2][4];
            {
                float ts[4][4];
#pragma unroll
                for (int px = 0; px < 4; ++px)
#pragma unroll
                    for (int cp = 0; cp < 2; ++cp) up2(tb8[px * 2 + cp], ts[px][2 * cp], ts[px][2 * cp + 1]);
#pragma unroll
                for (int pr = 0; pr < 2; ++pr)
#pragma unroll
                    for (int i = 0; i < 4; ++i) tpp[pr][i] = pk2(ts[2 * pr][i], ts[2 * pr + 1][i]);
            }

            float4 w2v = ldg4(out2_w + r * 128 + o4);
            ull wd[4] = {dup2(w2v.x), dup2(w2v.y), dup2(w2v.z), dup2(w2v.w)};

#pragma unroll 1
            for (int jp = 0; jp < 2; ++jp) {
                ull us[16];
#pragma unroll
                for (int tt = 0; tt < 16; ++tt) us[tt] = pk2(0.f, 0.f);
                mv2<128, 2, 1, 384>(g_WB + r * 128, sc + jp * 1024, 512, o4, us);
#pragma unroll
                for (int row = 0; row < 2; ++row)
#pragma unroll
                    for (int pr = 0; pr < 2; ++pr)
#pragma unroll
                        for (int i = 0; i < 4; ++i)
                            s2[jp * 2 + row][pr] = fma2(gelu_e2(add2(tpp[pr][i], us[row * 8 + pr * 4 + i])),
                                                        wd[i], s2[jp * 2 + row][pr]);
            }
        }

        const float o2b = __ldg(out2_b);
#pragma unroll
        for (int j = 0; j < 4; ++j)
#pragma unroll
            for (int pr = 0; pr < 2; ++pr) {
                ull tt = wsum2(s2[j][pr]);
                float a, bv; up2(tt, a, bv);
                if (ln == 0) {
                    sa[pr * 2][j] = a + o2b;
                    sa[pr * 2 + 1][j] = bv + o2b;
                }
            }
        __syncwarp();

        if (ln < 16) {
            int p = ln >> 2, j = ln & 3;
            float l0 = sa[p][0], l1 = sa[p][1], l2 = sa[p][2], l3 = sa[p][3];
            float mx = fmaxf(fmaxf(l0, l1), fmaxf(l2, l3));
            float den = expf(l0 - mx) + expf(l1 - mx) + expf(l2 - mx) + expf(l3 - mx);
            float e = expf(sa[p][j] - mx);
            out[(((size_t)b * 4 + j) * kHu + hu) * kWu + wu0 + p] = e / den;
        }
    }
}

extern "C" void kernel_launch(void* const* d_in, const int* in_sizes, int n_in,
                              void* d_out, int out_size) {
    const float* feat     = (const float*)d_in[0];
    const float* featup   = (const float*)d_in[1];
    const float* ctx_ln_b = (const float*)d_in[2];
    const float* q_w      = (const float*)d_in[3];
    const float* q_b      = (const float*)d_in[4];
    const float* k_w      = (const float*)d_in[5];
    const float* k_b      = (const float*)d_in[6];
    const float* v_w      = (const float*)d_in[7];
    const float* v_b      = (const float*)d_in[8];
    const float* o_w      = (const float*)d_in[9];
    const float* o_b      = (const float*)d_in[10];
    const float* fc1_w    = (const float*)d_in[11];
    const float* fc1_b    = (const float*)d_in[12];
    const float* fc2_w    = (const float*)d_in[13];
    const float* fc2_b    = (const float*)d_in[14];
    const float* out1_w   = (const float*)d_in[15];
    const float* out1_b   = (const float*)d_in[16];
    const float* out2_w   = (const float*)d_in[17];
    const float* out2_b   = (const float*)d_in[18];
    const float* ctx_ln_g = (const float*)d_in[19];

    prep_kernel<<<(128 * 384 + 255) / 256, 256>>>(out1_w);
    upsample_tf_kernel<<<kN / 8, 64>>>(
        feat, featup, ctx_ln_b, q_w, q_b, k_w, k_b, v_w, v_b, o_w, o_b,
        fc1_w, fc1_b, fc2_w, fc2_b, out1_b, out2_w, out2_b, ctx_ln_g,
        (float*)d_out);
}